// round 2
// baseline (speedup 1.0000x reference)
#include <cuda_runtime.h>
#include <math.h>
#include <stdint.h>

#define BB 4096
#define IND 2048
#define SS 8
#define DD 256
#define KK 8192
#define SD 2048   // S*D

// ------------- device-global scratch (no runtime allocation allowed) -----
__device__ float g_z[(size_t)BB * SD];
__device__ float g_quant[(size_t)BB * SD];
__device__ float g_recon[(size_t)BB * IND];
__device__ float g_zsq[BB * SS];
__device__ float g_esq[SS * KK];
__device__ int   g_codes[BB * SS];
__device__ float g_counts[SS * KK];

// ------------- fp32 GEMM: C[M,N] = A[M,Kd] @ Wt[N,Kd]^T + bias[N] --------
__global__ __launch_bounds__(256) void gemm_nt(const float* __restrict__ A,
                                               const float* __restrict__ Wt,
                                               const float* __restrict__ bias,
                                               float* __restrict__ C,
                                               int M, int N, int Kd) {
  __shared__ __align__(16) float xs[16][68];
  __shared__ __align__(16) float ws[16][68];
  int tid = threadIdx.x;
  int ty = tid >> 4, tx = tid & 15;
  int row0 = blockIdx.y << 6, col0 = blockIdx.x << 6;
  int lrow = tid >> 2, lk4 = (tid & 3) << 2;
  float acc[4][4] = {};
  for (int k0 = 0; k0 < Kd; k0 += 16) {
    float4 a4 = *(const float4*)(A + (size_t)(row0 + lrow) * Kd + k0 + lk4);
    float4 b4 = *(const float4*)(Wt + (size_t)(col0 + lrow) * Kd + k0 + lk4);
    __syncthreads();
    xs[lk4 + 0][lrow] = a4.x; xs[lk4 + 1][lrow] = a4.y;
    xs[lk4 + 2][lrow] = a4.z; xs[lk4 + 3][lrow] = a4.w;
    ws[lk4 + 0][lrow] = b4.x; ws[lk4 + 1][lrow] = b4.y;
    ws[lk4 + 2][lrow] = b4.z; ws[lk4 + 3][lrow] = b4.w;
    __syncthreads();
#pragma unroll
    for (int kk = 0; kk < 16; kk++) {
      float4 av = *(const float4*)&xs[kk][ty << 2];
      float4 bv = *(const float4*)&ws[kk][tx << 2];
      float ar[4] = {av.x, av.y, av.z, av.w};
      float br[4] = {bv.x, bv.y, bv.z, bv.w};
#pragma unroll
      for (int i = 0; i < 4; i++)
#pragma unroll
        for (int j = 0; j < 4; j++) acc[i][j] += ar[i] * br[j];
    }
  }
#pragma unroll
  for (int i = 0; i < 4; i++) {
    int r = row0 + (ty << 2) + i;
    int c = col0 + (tx << 2);
    float4 o;
    o.x = acc[i][0] + bias[c + 0];
    o.y = acc[i][1] + bias[c + 1];
    o.z = acc[i][2] + bias[c + 2];
    o.w = acc[i][3] + bias[c + 3];
    *(float4*)(C + (size_t)r * N + c) = o;
  }
}

// ------------- row sum-of-squares over 256-wide rows (1 warp / row) ------
__global__ void rowsq_kernel(const float* __restrict__ in,
                             float* __restrict__ out, int nrows) {
  int w = (blockIdx.x * blockDim.x + threadIdx.x) >> 5;
  int lane = threadIdx.x & 31;
  if (w >= nrows) return;
  const float* p = in + (size_t)w * DD;
  float s = 0.f;
#pragma unroll
  for (int i = 0; i < 8; i++) { float v = p[lane + 32 * i]; s += v * v; }
#pragma unroll
  for (int o = 16; o; o >>= 1) s += __shfl_xor_sync(0xffffffffu, s, o);
  if (lane == 0) out[w] = s;
}

__global__ void zero_kernel(float* __restrict__ p, int n) {
  int i = blockIdx.x * blockDim.x + threadIdx.x;
  if (i < n) p[i] = 0.f;
}

__device__ __forceinline__ unsigned long long packdk(float d, int k) {
  unsigned u = __float_as_uint(d);
  u = (u & 0x80000000u) ? ~u : (u | 0x80000000u);
  return ((unsigned long long)u << 32) | (unsigned)k;
}

// ------------- fused distance GEMM + argmin ------------------------------
// grid (B/32, S); block 128. Each block: 32 b-rows x all 8192 codes.
// dyn smem: zs 32x256 f32 (swizzled) + cbs 64x256 f32 (swizzled) + red 512 u64
__global__ __launch_bounds__(128) void argmin_kernel(
    const float* __restrict__ z, const float* __restrict__ cb,
    const float* __restrict__ zsq, const float* __restrict__ esq,
    int* __restrict__ codes) {
  extern __shared__ float sm[];
  float4* zs4 = (float4*)sm;                       // 32 rows x 64 float4
  float4* cbs4 = (float4*)(sm + 32 * 256);         // 64 rows x 64 float4
  unsigned long long* red = (unsigned long long*)(sm + 32 * 256 + 64 * 256);

  int tid = threadIdx.x;
  int s = blockIdx.y;
  int b0 = blockIdx.x << 5;
  int ty = tid >> 4;   // 0..7  -> rows 4*ty..4*ty+3
  int tx = tid & 15;   // 0..15 -> ks tx+16j

  // load z tile (swizzled)
#pragma unroll
  for (int l = 0; l < 16; l++) {
    int idx4 = tid + l * 128;          // 0..2047
    int r = idx4 >> 6;
    int d4 = idx4 & 63;
    float4 v = *(const float4*)(z + (size_t)(b0 + r) * SD + s * DD + (d4 << 2));
    zs4[r * 64 + (d4 ^ (r & 7))] = v;
  }

  float zsqv[4];
#pragma unroll
  for (int i = 0; i < 4; i++) zsqv[i] = zsq[(b0 + (ty << 2) + i) * SS + s];

  float bestd[4];
  int bestk[4];
#pragma unroll
  for (int i = 0; i < 4; i++) { bestd[i] = 3.4e38f; bestk[i] = 0; }

  int txm = tx & 7;
  for (int kt = 0; kt < KK; kt += 64) {
    __syncthreads();
#pragma unroll
    for (int l = 0; l < 32; l++) {
      int idx4 = tid + l * 128;        // 0..4095
      int kk = idx4 >> 6;
      int d4 = idx4 & 63;
      float4 v = *(const float4*)(cb + ((size_t)(s * KK + kt + kk)) * DD + (d4 << 2));
      cbs4[kk * 64 + (d4 ^ (kk & 7))] = v;
    }
    __syncthreads();

    float acc[4][4] = {};
#pragma unroll 2
    for (int d4 = 0; d4 < 64; d4++) {
      float4 za[4];
#pragma unroll
      for (int i = 0; i < 4; i++) {
        int r = (ty << 2) + i;
        za[i] = zs4[r * 64 + (d4 ^ (r & 7))];
      }
      int cc = d4 ^ txm;
#pragma unroll
      for (int j = 0; j < 4; j++) {
        float4 bv = cbs4[(tx + 16 * j) * 64 + cc];
#pragma unroll
        for (int i = 0; i < 4; i++) {
          acc[i][j] += za[i].x * bv.x;
          acc[i][j] += za[i].y * bv.y;
          acc[i][j] += za[i].z * bv.z;
          acc[i][j] += za[i].w * bv.w;
        }
      }
    }
    // epilogue in reference order: (zsq + esq) - 2*cross, fp32
#pragma unroll
    for (int j = 0; j < 4; j++) {
      int kg = kt + tx + 16 * j;
      float e = esq[(s << 13) + kg];
#pragma unroll
      for (int i = 0; i < 4; i++) {
        float t = zsqv[i] + e;
        float dv = t - 2.0f * acc[i][j];
        if (dv < bestd[i]) { bestd[i] = dv; bestk[i] = kg; }
      }
    }
  }
  __syncthreads();
#pragma unroll
  for (int i = 0; i < 4; i++) {
    int r = (ty << 2) + i;
    red[r * 16 + tx] = packdk(bestd[i], bestk[i]);
  }
  __syncthreads();
  if (tid < 32) {
    unsigned long long m = red[tid * 16];
#pragma unroll
    for (int j = 1; j < 16; j++) {
      unsigned long long v = red[tid * 16 + j];
      if (v < m) m = v;
    }
    codes[(b0 + tid) * SS + s] = (int)(m & 0xffffffffULL);
  }
}

// ------------- gather quantized vectors ----------------------------------
__global__ void gather_kernel(const float* __restrict__ cb,
                              const int* __restrict__ codes,
                              float* __restrict__ quant) {
  int i = blockIdx.x * blockDim.x + threadIdx.x;  // float4 index
  int b = i >> 9, rem = i & 511;
  int s = rem >> 6, d4 = rem & 63;
  int code = codes[b * SS + s];
  float4 v = *(const float4*)(cb + ((size_t)(s * KK + code)) * DD + (d4 << 2));
  *(float4*)(quant + (size_t)b * SD + s * DD + (d4 << 2)) = v;
}

__global__ void count_kernel(const int* __restrict__ codes,
                             float* __restrict__ counts) {
  int i = blockIdx.x * blockDim.x + threadIdx.x;
  if (i < BB * SS) {
    int s = i & 7;
    atomicAdd(&counts[s * KK + codes[i]], 1.0f);
  }
}

__global__ void perp_kernel(const float* __restrict__ counts,
                            float* __restrict__ outp) {
  __shared__ float sh[256];
  __shared__ float perps;
  int tid = threadIdx.x;
  if (tid == 0) perps = 0.f;
  for (int s = 0; s < SS; s++) {
    float local = 0.f;
    for (int k = tid; k < KK; k += 256) {
      float p = counts[s * KK + k] * (1.0f / BB);
      local += p * logf(p + 1e-10f);
    }
    sh[tid] = local;
    __syncthreads();
    for (int o = 128; o; o >>= 1) {
      if (tid < o) sh[tid] += sh[tid + o];
      __syncthreads();
    }
    if (tid == 0) perps += expf(-sh[0]);
    __syncthreads();
  }
  if (tid == 0) *outp = perps * (1.0f / SS);
}

__global__ void copy4_kernel(float* __restrict__ dst,
                             const float* __restrict__ src, int n4) {
  int i = blockIdx.x * blockDim.x + threadIdx.x;
  if (i < n4) ((float4*)dst)[i] = ((const float4*)src)[i];
}

__global__ void codesf_kernel(float* __restrict__ dst,
                              const int* __restrict__ codes, int n) {
  int i = blockIdx.x * blockDim.x + threadIdx.x;
  if (i < n) dst[i] = (float)codes[i];
}

// --------------------------------------------------------------------------
extern "C" void kernel_launch(void* const* d_in, const int* in_sizes, int n_in,
                              void* d_out, int out_size) {
  const float* x     = (const float*)d_in[0];
  const float* enc_w = (const float*)d_in[1];
  const float* enc_b = (const float*)d_in[2];
  const float* cb    = (const float*)d_in[3];
  const float* dec_w = (const float*)d_in[4];
  const float* dec_b = (const float*)d_in[5];

  float *z, *quant, *recon, *zsq, *esq, *counts;
  int* codes;
  cudaGetSymbolAddress((void**)&z, g_z);
  cudaGetSymbolAddress((void**)&quant, g_quant);
  cudaGetSymbolAddress((void**)&recon, g_recon);
  cudaGetSymbolAddress((void**)&zsq, g_zsq);
  cudaGetSymbolAddress((void**)&esq, g_esq);
  cudaGetSymbolAddress((void**)&counts, g_counts);
  cudaGetSymbolAddress((void**)&codes, g_codes);

  const int offQ = BB * IND;            // 8388608
  const int offC = offQ + BB * SD;      // 16777216
  const int offP = offC + BB * SS;      // 16809984
  float* out = (float*)d_out;
  float* reconDst = (out_size >= offQ) ? out : recon;

  cudaFuncSetAttribute(argmin_kernel,
                       cudaFuncAttributeMaxDynamicSharedMemorySize, 102400);

  // 1. encoder: z = x @ enc_w^T + enc_b
  gemm_nt<<<dim3(SD / 64, BB / 64), 256>>>(x, enc_w, enc_b, z, BB, SD, IND);
  // 2. norms
  rowsq_kernel<<<BB * SS / 8, 256>>>(z, zsq, BB * SS);
  rowsq_kernel<<<SS * KK / 8, 256>>>(cb, esq, SS * KK);
  // 3. distance GEMM + argmin
  argmin_kernel<<<dim3(BB / 32, SS), 128, 102400>>>(z, cb, zsq, esq, codes);
  // 4. gather quantized
  gather_kernel<<<BB * SD / 4 / 256, 256>>>(cb, codes, quant);
  // 5. code counts
  zero_kernel<<<SS * KK / 256, 256>>>(counts, SS * KK);
  count_kernel<<<BB * SS / 256, 256>>>(codes, counts);
  // 6. decoder: x_recon = quant @ dec_w^T + dec_b
  gemm_nt<<<dim3(IND / 64, BB / 64), 256>>>(quant, dec_w, dec_b, reconDst,
                                            BB, IND, SD);
  // 7. optional tuple tail
  if (out_size >= offC)
    copy4_kernel<<<BB * SD / 4 / 256, 256>>>(out + offQ, quant, BB * SD / 4);
  if (out_size >= offP)
    codesf_kernel<<<BB * SS / 256, 256>>>(out + offC, codes, BB * SS);
  if (out_size >= offP + 1)
    perp_kernel<<<1, 256>>>(counts, out + offP);
}

// round 5
// speedup vs baseline: 2.5862x; 2.5862x over previous
#include <cuda_runtime.h>
#include <cuda_bf16.h>
#include <math.h>
#include <stdint.h>

#define BB 4096
#define IND 2048
#define SS 8
#define DD 256
#define KK 8192
#define SD 2048   // S*D

#define CAP 96
#define MARGIN 2e-4f

// ------------- device-global scratch -------------------------------------
__device__ float g_z[(size_t)BB * SD];
__device__ float g_quant[(size_t)BB * SD];
__device__ float g_recon[(size_t)BB * IND];
__device__ float g_zsq[BB * SS];
__device__ float g_esq[SS * KK];
__device__ int   g_codes[BB * SS];
__device__ float g_counts[SS * KK];
__device__ int   g_flags[BB * SS];
__device__ __nv_bfloat16 g_zb[(size_t)BB * SD];
__device__ __nv_bfloat16 g_cbb[(size_t)SS * KK * DD];
__device__ __nv_bfloat16 g_capx[(size_t)BB * SS * KK];   // approx cross

// ------------- fp32 GEMM (bit-faithful sequential-k): C = A @ Wt^T + b ---
__global__ __launch_bounds__(256) void gemm_nt(const float* __restrict__ A,
                                               const float* __restrict__ Wt,
                                               const float* __restrict__ bias,
                                               float* __restrict__ C,
                                               int M, int N, int Kd) {
  __shared__ __align__(16) float xs[16][68];
  __shared__ __align__(16) float ws[16][68];
  int tid = threadIdx.x;
  int ty = tid >> 4, tx = tid & 15;
  int row0 = blockIdx.y << 6, col0 = blockIdx.x << 6;
  int lrow = tid >> 2, lk4 = (tid & 3) << 2;
  float acc[4][4] = {};
  for (int k0 = 0; k0 < Kd; k0 += 16) {
    float4 a4 = *(const float4*)(A + (size_t)(row0 + lrow) * Kd + k0 + lk4);
    float4 b4 = *(const float4*)(Wt + (size_t)(col0 + lrow) * Kd + k0 + lk4);
    __syncthreads();
    xs[lk4 + 0][lrow] = a4.x; xs[lk4 + 1][lrow] = a4.y;
    xs[lk4 + 2][lrow] = a4.z; xs[lk4 + 3][lrow] = a4.w;
    ws[lk4 + 0][lrow] = b4.x; ws[lk4 + 1][lrow] = b4.y;
    ws[lk4 + 2][lrow] = b4.z; ws[lk4 + 3][lrow] = b4.w;
    __syncthreads();
#pragma unroll
    for (int kk = 0; kk < 16; kk++) {
      float4 av = *(const float4*)&xs[kk][ty << 2];
      float4 bv = *(const float4*)&ws[kk][tx << 2];
      float ar[4] = {av.x, av.y, av.z, av.w};
      float br[4] = {bv.x, bv.y, bv.z, bv.w};
#pragma unroll
      for (int i = 0; i < 4; i++)
#pragma unroll
        for (int j = 0; j < 4; j++) acc[i][j] += ar[i] * br[j];
    }
  }
#pragma unroll
  for (int i = 0; i < 4; i++) {
    int r = row0 + (ty << 2) + i;
    int c = col0 + (tx << 2);
    float4 o;
    o.x = acc[i][0] + bias[c + 0];
    o.y = acc[i][1] + bias[c + 1];
    o.z = acc[i][2] + bias[c + 2];
    o.w = acc[i][3] + bias[c + 3];
    *(float4*)(C + (size_t)r * N + c) = o;
  }
}

// ------------- row sum-of-squares (order is load-bearing) ----------------
__global__ void rowsq_kernel(const float* __restrict__ in,
                             float* __restrict__ out, int nrows) {
  int w = (blockIdx.x * blockDim.x + threadIdx.x) >> 5;
  int lane = threadIdx.x & 31;
  if (w >= nrows) return;
  const float* p = in + (size_t)w * DD;
  float s = 0.f;
#pragma unroll
  for (int i = 0; i < 8; i++) { float v = p[lane + 32 * i]; s += v * v; }
#pragma unroll
  for (int o = 16; o; o >>= 1) s += __shfl_xor_sync(0xffffffffu, s, o);
  if (lane == 0) out[w] = s;
}

__global__ void zero_kernel(float* __restrict__ p, int n) {
  int i = blockIdx.x * blockDim.x + threadIdx.x;
  if (i < n) p[i] = 0.f;
}

__global__ void tobf16_kernel(const float* __restrict__ in,
                              __nv_bfloat16* __restrict__ out, int n4) {
  int i = blockIdx.x * blockDim.x + threadIdx.x;
  if (i < n4) {
    float4 v = ((const float4*)in)[i];
    __nv_bfloat162 a = __floats2bfloat162_rn(v.x, v.y);
    __nv_bfloat162 b = __floats2bfloat162_rn(v.z, v.w);
    ((uint2*)out)[i] = make_uint2(*(uint32_t*)&a, *(uint32_t*)&b);
  }
}

__device__ __forceinline__ unsigned long long packdk(float d, int k) {
  unsigned u = __float_as_uint(d);
  u = (u & 0x80000000u) ? ~u : (u | 0x80000000u);
  return ((unsigned long long)u << 32) | (unsigned)k;
}

// ------------- bf16 HMMA mma.sync helper ---------------------------------
__device__ __forceinline__ void mma16816(float* c, const uint32_t* a,
                                         const uint32_t* b) {
  asm volatile(
      "mma.sync.aligned.m16n8k16.row.col.f32.bf16.bf16.f32 "
      "{%0,%1,%2,%3}, {%4,%5,%6,%7}, {%8,%9}, {%0,%1,%2,%3};"
      : "+f"(c[0]), "+f"(c[1]), "+f"(c[2]), "+f"(c[3])
      : "r"(a[0]), "r"(a[1]), "r"(a[2]), "r"(a[3]), "r"(b[0]), "r"(b[1]));
}

// ------------- phase 1: approx cross GEMM on HMMA ------------------------
// grid (KK/128, BB/128, SS); block 256 (8 warps: 2 M-halves x 4 N-quarters)
// tile: 128 rows x 128 codes x D=256 (4 smem k-chunks of 64)
__global__ __launch_bounds__(256) void cross_mma_kernel(
    const __nv_bfloat16* __restrict__ zb, const __nv_bfloat16* __restrict__ cbb,
    __nv_bfloat16* __restrict__ capx) {
  __shared__ __align__(16) __nv_bfloat16 As[128][72];
  __shared__ __align__(16) __nv_bfloat16 Bs[128][72];
  int tid = threadIdx.x;
  int wid = tid >> 5, lane = tid & 31;
  int gid = lane >> 2, tig = lane & 3;
  int wm = wid & 1, wn = wid >> 1;
  int s = blockIdx.z, k0 = blockIdx.x << 7, b0 = blockIdx.y << 7;

  float acc[4][4][4];
#pragma unroll
  for (int mf = 0; mf < 4; mf++)
#pragma unroll
    for (int nf = 0; nf < 4; nf++)
#pragma unroll
      for (int q = 0; q < 4; q++) acc[mf][nf][q] = 0.f;

  for (int kc = 0; kc < 4; kc++) {
    int koff = kc * 64;
    __syncthreads();
#pragma unroll
    for (int l = 0; l < 4; l++) {
      int idx = tid + l * 256;          // 0..1023
      int r = idx >> 3, c8 = idx & 7;
      uint4 va = *(const uint4*)(zb + (size_t)(b0 + r) * SD + s * DD + koff + c8 * 8);
      *(uint4*)&As[r][c8 * 8] = va;
      uint4 vb = *(const uint4*)(cbb + ((size_t)s * KK + k0 + r) * DD + koff + c8 * 8);
      *(uint4*)&Bs[r][c8 * 8] = vb;
    }
    __syncthreads();

#pragma unroll
    for (int kk = 0; kk < 4; kk++) {
      int k16 = kk * 16;
      uint32_t a[4][4];
#pragma unroll
      for (int mf = 0; mf < 4; mf++) {
        int R = wm * 64 + mf * 16;
        a[mf][0] = *(const uint32_t*)&As[R + gid][k16 + 2 * tig];
        a[mf][1] = *(const uint32_t*)&As[R + gid + 8][k16 + 2 * tig];
        a[mf][2] = *(const uint32_t*)&As[R + gid][k16 + 8 + 2 * tig];
        a[mf][3] = *(const uint32_t*)&As[R + gid + 8][k16 + 8 + 2 * tig];
      }
#pragma unroll
      for (int nf = 0; nf < 4; nf++) {
        int C = wn * 32 + nf * 8;
        uint32_t b[2];
        b[0] = *(const uint32_t*)&Bs[C + gid][k16 + 2 * tig];
        b[1] = *(const uint32_t*)&Bs[C + gid][k16 + 8 + 2 * tig];
#pragma unroll
        for (int mf = 0; mf < 4; mf++) mma16816(acc[mf][nf], a[mf], b);
      }
    }
  }

  // epilogue: pack fp32 accum -> bf16, store to capx
#pragma unroll
  for (int mf = 0; mf < 4; mf++) {
    int row0 = wm * 64 + mf * 16 + gid;
#pragma unroll
    for (int nf = 0; nf < 4; nf++) {
      int col = k0 + wn * 32 + nf * 8 + 2 * tig;
      __nv_bfloat162 lo = __floats2bfloat162_rn(acc[mf][nf][0], acc[mf][nf][1]);
      __nv_bfloat162 hi = __floats2bfloat162_rn(acc[mf][nf][2], acc[mf][nf][3]);
      size_t g0 = ((size_t)s * BB + b0 + row0) * KK + col;
      size_t g1 = ((size_t)s * BB + b0 + row0 + 8) * KK + col;
      *(uint32_t*)(capx + g0) = *(uint32_t*)&lo;
      *(uint32_t*)(capx + g1) = *(uint32_t*)&hi;
    }
  }
}

// ------------- phase 2: scan + exact recheck of candidates ---------------
__global__ __launch_bounds__(256) void scan_kernel(
    const float* __restrict__ z, const float* __restrict__ cb,
    const __nv_bfloat16* __restrict__ capx, const float* __restrict__ zsq,
    const float* __restrict__ esq, int* __restrict__ codes,
    int* __restrict__ flags) {
  __shared__ __align__(16) __nv_bfloat16 crow[KK];
  __shared__ float zrow[DD];
  __shared__ float redf[8];
  __shared__ float bmax;
  __shared__ int cnt;
  __shared__ int cand[CAP];
  __shared__ unsigned long long packs[CAP];
  int srow = blockIdx.x;
  int s = srow >> 12, b = srow & 4095;
  int tid = threadIdx.x;
  const uint4* src = (const uint4*)(capx + (size_t)srow * KK);
  uint4* dc = (uint4*)crow;
#pragma unroll
  for (int l = 0; l < 4; l++) dc[tid + l * 256] = src[tid + l * 256];
  zrow[tid] = z[(size_t)b * SD + s * DD + tid];
  if (tid == 0) cnt = 0;
  __syncthreads();

  float mx = -1e30f;
#pragma unroll
  for (int l = 0; l < 32; l++)
    mx = fmaxf(mx, __bfloat162float(crow[tid + l * 256]));
#pragma unroll
  for (int o = 16; o; o >>= 1) mx = fmaxf(mx, __shfl_xor_sync(~0u, mx, o));
  if ((tid & 31) == 0) redf[tid >> 5] = mx;
  __syncthreads();
  if (tid == 0) {
    float m = redf[0];
#pragma unroll
    for (int i = 1; i < 8; i++) m = fmaxf(m, redf[i]);
    bmax = m;
  }
  __syncthreads();
  float th = bmax - MARGIN;
#pragma unroll
  for (int l = 0; l < 32; l++) {
    int k = tid + l * 256;
    if (__bfloat162float(crow[k]) >= th) {
      int p = atomicAdd(&cnt, 1);
      if (p < CAP) cand[p] = k;
    }
  }
  __syncthreads();
  int n = cnt;
  if (tid == 0) flags[srow] = (n > CAP) ? 1 : 0;
  if (n > CAP) return;

  if (tid < n) {
    int k = cand[tid];
    const float* e = cb + ((size_t)s * KK + k) * DD;
    float acc = 0.f;
#pragma unroll 8
    for (int d = 0; d < DD; d += 4) {
      float4 ev = *(const float4*)(e + d);
      acc = fmaf(zrow[d + 0], ev.x, acc);
      acc = fmaf(zrow[d + 1], ev.y, acc);
      acc = fmaf(zrow[d + 2], ev.z, acc);
      acc = fmaf(zrow[d + 3], ev.w, acc);
    }
    float t = zsq[b * SS + s] + esq[s * KK + k];
    float dv = t - 2.0f * acc;
    packs[tid] = packdk(dv, k);
  }
  __syncthreads();
  if (tid == 0) {
    unsigned long long m = packs[0];
    for (int i = 1; i < n; i++) { unsigned long long v = packs[i]; if (v < m) m = v; }
    codes[b * SS + s] = (int)(m & 0xffffffffULL);
  }
}

// ------------- fallback: full exact scan for overflowed rows (rare) ------
__global__ __launch_bounds__(256) void fallback_kernel(
    const float* __restrict__ z, const float* __restrict__ cb,
    const float* __restrict__ zsq, const float* __restrict__ esq,
    int* __restrict__ codes, const int* __restrict__ flags) {
  if (!flags[blockIdx.x]) return;
  __shared__ float zrow[DD];
  __shared__ unsigned long long red[256];
  int srow = blockIdx.x;
  int s = srow >> 12, b = srow & 4095;
  int tid = threadIdx.x;
  zrow[tid] = z[(size_t)b * SD + s * DD + tid];
  __syncthreads();
  float zsqv = zsq[b * SS + s];
  unsigned long long best = ~0ull;
  for (int j = 0; j < 32; j++) {
    int k = tid + j * 256;
    const float* e = cb + ((size_t)s * KK + k) * DD;
    float acc = 0.f;
#pragma unroll 8
    for (int d = 0; d < DD; d += 4) {
      float4 ev = *(const float4*)(e + d);
      acc = fmaf(zrow[d + 0], ev.x, acc);
      acc = fmaf(zrow[d + 1], ev.y, acc);
      acc = fmaf(zrow[d + 2], ev.z, acc);
      acc = fmaf(zrow[d + 3], ev.w, acc);
    }
    float dv = (zsqv + esq[s * KK + k]) - 2.0f * acc;
    unsigned long long p = packdk(dv, k);
    if (p < best) best = p;
  }
  red[tid] = best;
  __syncthreads();
  for (int o = 128; o; o >>= 1) {
    if (tid < o) { unsigned long long v = red[tid + o]; if (v < red[tid]) red[tid] = v; }
    __syncthreads();
  }
  if (tid == 0) codes[b * SS + s] = (int)(red[0] & 0xffffffffULL);
}

// ------------- tail kernels ----------------------------------------------
__global__ void gather_kernel(const float* __restrict__ cb,
                              const int* __restrict__ codes,
                              float* __restrict__ quant) {
  int i = blockIdx.x * blockDim.x + threadIdx.x;
  int b = i >> 9, rem = i & 511;
  int s = rem >> 6, d4 = rem & 63;
  int code = codes[b * SS + s];
  float4 v = *(const float4*)(cb + ((size_t)(s * KK + code)) * DD + (d4 << 2));
  *(float4*)(quant + (size_t)b * SD + s * DD + (d4 << 2)) = v;
}

__global__ void count_kernel(const int* __restrict__ codes,
                             float* __restrict__ counts) {
  int i = blockIdx.x * blockDim.x + threadIdx.x;
  if (i < BB * SS) {
    int s = i & 7;
    atomicAdd(&counts[s * KK + codes[i]], 1.0f);
  }
}

__global__ void perp_kernel(const float* __restrict__ counts,
                            float* __restrict__ outp) {
  __shared__ float sh[256];
  __shared__ float perps;
  int tid = threadIdx.x;
  if (tid == 0) perps = 0.f;
  for (int s = 0; s < SS; s++) {
    float local = 0.f;
    for (int k = tid; k < KK; k += 256) {
      float p = counts[s * KK + k] * (1.0f / BB);
      local += p * logf(p + 1e-10f);
    }
    sh[tid] = local;
    __syncthreads();
    for (int o = 128; o; o >>= 1) {
      if (tid < o) sh[tid] += sh[tid + o];
      __syncthreads();
    }
    if (tid == 0) perps += expf(-sh[0]);
    __syncthreads();
  }
  if (tid == 0) *outp = perps * (1.0f / SS);
}

__global__ void copy4_kernel(float* __restrict__ dst,
                             const float* __restrict__ src, int n4) {
  int i = blockIdx.x * blockDim.x + threadIdx.x;
  if (i < n4) ((float4*)dst)[i] = ((const float4*)src)[i];
}

__global__ void codesf_kernel(float* __restrict__ dst,
                              const int* __restrict__ codes, int n) {
  int i = blockIdx.x * blockDim.x + threadIdx.x;
  if (i < n) dst[i] = (float)codes[i];
}

// --------------------------------------------------------------------------
extern "C" void kernel_launch(void* const* d_in, const int* in_sizes, int n_in,
                              void* d_out, int out_size) {
  const float* x     = (const float*)d_in[0];
  const float* enc_w = (const float*)d_in[1];
  const float* enc_b = (const float*)d_in[2];
  const float* cb    = (const float*)d_in[3];
  const float* dec_w = (const float*)d_in[4];
  const float* dec_b = (const float*)d_in[5];

  float *z, *quant, *recon, *zsq, *esq, *counts;
  int *codes, *flags;
  __nv_bfloat16 *zb, *cbb, *capx;
  cudaGetSymbolAddress((void**)&z, g_z);
  cudaGetSymbolAddress((void**)&quant, g_quant);
  cudaGetSymbolAddress((void**)&recon, g_recon);
  cudaGetSymbolAddress((void**)&zsq, g_zsq);
  cudaGetSymbolAddress((void**)&esq, g_esq);
  cudaGetSymbolAddress((void**)&counts, g_counts);
  cudaGetSymbolAddress((void**)&codes, g_codes);
  cudaGetSymbolAddress((void**)&flags, g_flags);
  cudaGetSymbolAddress((void**)&zb, g_zb);
  cudaGetSymbolAddress((void**)&cbb, g_cbb);
  cudaGetSymbolAddress((void**)&capx, g_capx);

  const int offQ = BB * IND;
  const int offC = offQ + BB * SD;
  const int offP = offC + BB * SS;
  float* out = (float*)d_out;
  float* reconDst = (out_size >= offQ) ? out : recon;

  // 1. encoder (fp32): z = x @ enc_w^T + enc_b
  gemm_nt<<<dim3(SD / 64, BB / 64), 256>>>(x, enc_w, enc_b, z, BB, SD, IND);
  // 2. norms (unchanged reduction order)
  rowsq_kernel<<<BB * SS / 8, 256>>>(z, zsq, BB * SS);
  rowsq_kernel<<<SS * KK / 8, 256>>>(cb, esq, SS * KK);
  // 3. bf16 conversions
  tobf16_kernel<<<BB * SD / 4 / 256, 256>>>(z, zb, BB * SD / 4);
  tobf16_kernel<<<SS * KK * DD / 4 / 256, 256>>>(cb, cbb, SS * KK * DD / 4);
  // 4. approx cross on HMMA tensor cores
  cross_mma_kernel<<<dim3(KK / 128, BB / 128, SS), 256>>>(zb, cbb, capx);
  // 5. scan + exact candidate recheck
  scan_kernel<<<BB * SS, 256>>>(z, cb, capx, zsq, esq, codes, flags);
  fallback_kernel<<<BB * SS, 256>>>(z, cb, zsq, esq, codes, flags);
  // 6. gather + counts
  gather_kernel<<<BB * SD / 4 / 256, 256>>>(cb, codes, quant);
  zero_kernel<<<SS * KK / 256, 256>>>(counts, SS * KK);
  count_kernel<<<BB * SS / 256, 256>>>(codes, counts);
  // 7. decoder (fp32): x_recon = quant @ dec_w^T + dec_b
  gemm_nt<<<dim3(IND / 64, BB / 64), 256>>>(quant, dec_w, dec_b, reconDst,
                                            BB, IND, SD);
  // 8. tuple tail
  if (out_size >= offC)
    copy4_kernel<<<BB * SD / 4 / 256, 256>>>(out + offQ, quant, BB * SD / 4);
  if (out_size >= offP)
    codesf_kernel<<<BB * SS / 256, 256>>>(out + offC, codes, BB * SS);
  if (out_size >= offP + 1)
    perp_kernel<<<1, 256>>>(counts, out + offP);
}

// round 10
// speedup vs baseline: 3.2324x; 1.2499x over previous
#include <cuda_runtime.h>
#include <cuda_bf16.h>
#include <cuda_fp16.h>
#include <math.h>
#include <stdint.h>

#define BB 4096
#define IND 2048
#define SS 8
#define DD 256
#define KK 8192
#define SD 2048   // S*D

#define CAP 96
#define MARGIN 2e-4f

// ------------- device-global scratch -------------------------------------
__device__ float g_z[(size_t)BB * SD];
__device__ float g_quant[(size_t)BB * SD];
__device__ float g_recon[(size_t)BB * IND];
__device__ float g_zsq[BB * SS];
__device__ float g_esq[SS * KK];
__device__ int   g_codes[BB * SS];
__device__ float g_counts[SS * KK];
__device__ int   g_flags[BB * SS];
__device__ __nv_bfloat16 g_zb[(size_t)BB * SD];
__device__ __nv_bfloat16 g_cbb[(size_t)SS * KK * DD];
__device__ __nv_bfloat16 g_capx[(size_t)BB * SS * KK];   // approx cross
// fp16 split operands (decoder only — encoder must stay bit-exact fp32)
__device__ __half g_dwh[(size_t)IND * SD];
__device__ __half g_dwl[(size_t)IND * SD];
__device__ __half g_qh[(size_t)BB * SD];
__device__ __half g_ql[(size_t)BB * SD];

// ------------- f32x2 packed-FMA helpers (sm_100+ PTX) --------------------
__device__ __forceinline__ unsigned long long pk2(float x, float y) {
  unsigned long long r;
  asm("mov.b64 %0, {%1, %2};" : "=l"(r) : "f"(x), "f"(y));
  return r;
}
__device__ __forceinline__ void fma2(unsigned long long& d,
                                     unsigned long long a,
                                     unsigned long long b) {
  asm("fma.rn.f32x2 %0, %1, %2, %0;" : "+l"(d) : "l"(a), "l"(b));
}
__device__ __forceinline__ void upk2(float& x, float& y,
                                     unsigned long long a) {
  asm("mov.b64 {%0, %1}, %2;" : "=f"(x), "=f"(y) : "l"(a));
}

// ------------- fp32 GEMM via packed f32x2 FFMA ---------------------------
// Bit-identical per-output k-sequential FMA chain to the proven gemm_nt.
// grid (N/128, M/128); block 256; 8x8 outputs/thread; K-chunk 16.
__global__ __launch_bounds__(256) void gemm128x2(
    const float* __restrict__ A, const float* __restrict__ Wt,
    const float* __restrict__ bias, float* __restrict__ C, int M, int N,
    int Kd) {
  __shared__ __align__(16) float xs[16][132];
  __shared__ __align__(16) float ws[16][132];
  int tid = threadIdx.x;
  int ty = tid >> 4, tx = tid & 15;
  int row0 = blockIdx.y << 7, col0 = blockIdx.x << 7;
  int lrow = tid >> 1, lk8 = (tid & 1) << 3;

  unsigned long long acc[8][4];
#pragma unroll
  for (int i = 0; i < 8; i++)
#pragma unroll
    for (int j = 0; j < 4; j++) acc[i][j] = 0ull;

  for (int k0 = 0; k0 < Kd; k0 += 16) {
    float4 a0 = *(const float4*)(A + (size_t)(row0 + lrow) * Kd + k0 + lk8);
    float4 a1 = *(const float4*)(A + (size_t)(row0 + lrow) * Kd + k0 + lk8 + 4);
    float4 b0 = *(const float4*)(Wt + (size_t)(col0 + lrow) * Kd + k0 + lk8);
    float4 b1 = *(const float4*)(Wt + (size_t)(col0 + lrow) * Kd + k0 + lk8 + 4);
    __syncthreads();
    xs[lk8 + 0][lrow] = a0.x; xs[lk8 + 1][lrow] = a0.y;
    xs[lk8 + 2][lrow] = a0.z; xs[lk8 + 3][lrow] = a0.w;
    xs[lk8 + 4][lrow] = a1.x; xs[lk8 + 5][lrow] = a1.y;
    xs[lk8 + 6][lrow] = a1.z; xs[lk8 + 7][lrow] = a1.w;
    ws[lk8 + 0][lrow] = b0.x; ws[lk8 + 1][lrow] = b0.y;
    ws[lk8 + 2][lrow] = b0.z; ws[lk8 + 3][lrow] = b0.w;
    ws[lk8 + 4][lrow] = b1.x; ws[lk8 + 5][lrow] = b1.y;
    ws[lk8 + 6][lrow] = b1.z; ws[lk8 + 7][lrow] = b1.w;
    __syncthreads();
#pragma unroll
    for (int kk = 0; kk < 16; kk++) {
      float4 av0 = *(const float4*)&xs[kk][ty << 3];
      float4 av1 = *(const float4*)&xs[kk][(ty << 3) + 4];
      float4 bv0 = *(const float4*)&ws[kk][tx << 3];
      float4 bv1 = *(const float4*)&ws[kk][(tx << 3) + 4];
      unsigned long long b2[4];
      b2[0] = pk2(bv0.x, bv0.y); b2[1] = pk2(bv0.z, bv0.w);
      b2[2] = pk2(bv1.x, bv1.y); b2[3] = pk2(bv1.z, bv1.w);
      float ar[8] = {av0.x, av0.y, av0.z, av0.w, av1.x, av1.y, av1.z, av1.w};
#pragma unroll
      for (int i = 0; i < 8; i++) {
        unsigned long long a2 = pk2(ar[i], ar[i]);
#pragma unroll
        for (int j = 0; j < 4; j++) fma2(acc[i][j], a2, b2[j]);
      }
    }
  }
#pragma unroll
  for (int i = 0; i < 8; i++) {
    int r = row0 + (ty << 3) + i;
    int c = col0 + (tx << 3);
    float o[8];
#pragma unroll
    for (int j = 0; j < 4; j++) upk2(o[2 * j], o[2 * j + 1], acc[i][j]);
#pragma unroll
    for (int j = 0; j < 8; j++) o[j] += bias[c + j];
    *(float4*)(C + (size_t)r * N + c) = make_float4(o[0], o[1], o[2], o[3]);
    *(float4*)(C + (size_t)r * N + c + 4) = make_float4(o[4], o[5], o[6], o[7]);
  }
}

// ------------- split fp32 -> fp16 hi/lo with exact pow2 pre-scale --------
__global__ void split_kernel(const float* __restrict__ in,
                             __half* __restrict__ hi, __half* __restrict__ lo,
                             float scale, int n4) {
  int i = blockIdx.x * blockDim.x + threadIdx.x;
  if (i < n4) {
    float4 v = ((const float4*)in)[i];
    v.x *= scale; v.y *= scale; v.z *= scale; v.w *= scale;
    __half hx = __float2half_rn(v.x), hy = __float2half_rn(v.y);
    __half hz = __float2half_rn(v.z), hw = __float2half_rn(v.w);
    __half lx = __float2half_rn(v.x - __half2float(hx));
    __half ly = __float2half_rn(v.y - __half2float(hy));
    __half lz = __float2half_rn(v.z - __half2float(hz));
    __half lw = __float2half_rn(v.w - __half2float(hw));
    __half2 h0 = __halves2half2(hx, hy), h1 = __halves2half2(hz, hw);
    __half2 l0 = __halves2half2(lx, ly), l1 = __halves2half2(lz, lw);
    ((uint2*)hi)[i] = make_uint2(*(uint32_t*)&h0, *(uint32_t*)&h1);
    ((uint2*)lo)[i] = make_uint2(*(uint32_t*)&l0, *(uint32_t*)&l1);
  }
}

// ------------- fp16 mma helper -------------------------------------------
__device__ __forceinline__ void mmaf16(float* c, const uint32_t* a,
                                       const uint32_t* b) {
  asm volatile(
      "mma.sync.aligned.m16n8k16.row.col.f32.f16.f16.f32 "
      "{%0,%1,%2,%3}, {%4,%5,%6,%7}, {%8,%9}, {%0,%1,%2,%3};"
      : "+f"(c[0]), "+f"(c[1]), "+f"(c[2]), "+f"(c[3])
      : "r"(a[0]), "r"(a[1]), "r"(a[2]), "r"(a[3]), "r"(b[0]), "r"(b[1]));
}

// ------------- 3-product fp16-split GEMM (decoder): C = inv*(A@W^T)+b ----
__global__ __launch_bounds__(256) void gemm3h(
    const __half* __restrict__ Ah, const __half* __restrict__ Al,
    const __half* __restrict__ Wh, const __half* __restrict__ Wl,
    const float* __restrict__ bias, float* __restrict__ C, float inv, int M,
    int N, int Kd) {
  __shared__ __align__(16) __half Ahs[128][40];
  __shared__ __align__(16) __half Als[128][40];
  __shared__ __align__(16) __half Whs[128][40];
  __shared__ __align__(16) __half Wls[128][40];
  int tid = threadIdx.x;
  int wid = tid >> 5, lane = tid & 31;
  int gid = lane >> 2, tig = lane & 3;
  int wm = wid & 1, wn = wid >> 1;
  int row0 = blockIdx.y << 7, col0 = blockIdx.x << 7;

  float acc[4][4][4];
#pragma unroll
  for (int mf = 0; mf < 4; mf++)
#pragma unroll
    for (int nf = 0; nf < 4; nf++)
#pragma unroll
      for (int q = 0; q < 4; q++) acc[mf][nf][q] = 0.f;

  for (int k0 = 0; k0 < Kd; k0 += 32) {
    __syncthreads();
#pragma unroll
    for (int l = 0; l < 2; l++) {
      int idx = tid + l * 256;
      int r = idx >> 2, c8 = (idx & 3) * 8;
      size_t ga = (size_t)(row0 + r) * Kd + k0 + c8;
      size_t gw = (size_t)(col0 + r) * Kd + k0 + c8;
      *(uint4*)&Ahs[r][c8] = *(const uint4*)(Ah + ga);
      *(uint4*)&Als[r][c8] = *(const uint4*)(Al + ga);
      *(uint4*)&Whs[r][c8] = *(const uint4*)(Wh + gw);
      *(uint4*)&Wls[r][c8] = *(const uint4*)(Wl + gw);
    }
    __syncthreads();

#pragma unroll
    for (int kk = 0; kk < 2; kk++) {
      int k16 = kk * 16;
      uint32_t ah[4][4], al[4][4];
#pragma unroll
      for (int mf = 0; mf < 4; mf++) {
        int R = wm * 64 + mf * 16;
        ah[mf][0] = *(const uint32_t*)&Ahs[R + gid][k16 + 2 * tig];
        ah[mf][1] = *(const uint32_t*)&Ahs[R + gid + 8][k16 + 2 * tig];
        ah[mf][2] = *(const uint32_t*)&Ahs[R + gid][k16 + 8 + 2 * tig];
        ah[mf][3] = *(const uint32_t*)&Ahs[R + gid + 8][k16 + 8 + 2 * tig];
        al[mf][0] = *(const uint32_t*)&Als[R + gid][k16 + 2 * tig];
        al[mf][1] = *(const uint32_t*)&Als[R + gid + 8][k16 + 2 * tig];
        al[mf][2] = *(const uint32_t*)&Als[R + gid][k16 + 8 + 2 * tig];
        al[mf][3] = *(const uint32_t*)&Als[R + gid + 8][k16 + 8 + 2 * tig];
      }
#pragma unroll
      for (int nf = 0; nf < 4; nf++) {
        int Cc = wn * 32 + nf * 8;
        uint32_t bh[2], bl[2];
        bh[0] = *(const uint32_t*)&Whs[Cc + gid][k16 + 2 * tig];
        bh[1] = *(const uint32_t*)&Whs[Cc + gid][k16 + 8 + 2 * tig];
        bl[0] = *(const uint32_t*)&Wls[Cc + gid][k16 + 2 * tig];
        bl[1] = *(const uint32_t*)&Wls[Cc + gid][k16 + 8 + 2 * tig];
#pragma unroll
        for (int mf = 0; mf < 4; mf++) {
          mmaf16(acc[mf][nf], ah[mf], bh);
          mmaf16(acc[mf][nf], ah[mf], bl);
          mmaf16(acc[mf][nf], al[mf], bh);
        }
      }
    }
  }

#pragma unroll
  for (int mf = 0; mf < 4; mf++) {
    int r0 = row0 + wm * 64 + mf * 16 + gid;
#pragma unroll
    for (int nf = 0; nf < 4; nf++) {
      int c = col0 + wn * 32 + nf * 8 + 2 * tig;
      float b0 = bias[c], b1 = bias[c + 1];
      float2 lo = make_float2(acc[mf][nf][0] * inv + b0,
                              acc[mf][nf][1] * inv + b1);
      float2 hi = make_float2(acc[mf][nf][2] * inv + b0,
                              acc[mf][nf][3] * inv + b1);
      *(float2*)(C + (size_t)r0 * N + c) = lo;
      *(float2*)(C + (size_t)(r0 + 8) * N + c) = hi;
    }
  }
}

// ------------- row sum-of-squares (order is load-bearing) ----------------
__global__ void rowsq_kernel(const float* __restrict__ in,
                             float* __restrict__ out, int nrows) {
  int w = (blockIdx.x * blockDim.x + threadIdx.x) >> 5;
  int lane = threadIdx.x & 31;
  if (w >= nrows) return;
  const float* p = in + (size_t)w * DD;
  float s = 0.f;
#pragma unroll
  for (int i = 0; i < 8; i++) { float v = p[lane + 32 * i]; s += v * v; }
#pragma unroll
  for (int o = 16; o; o >>= 1) s += __shfl_xor_sync(0xffffffffu, s, o);
  if (lane == 0) out[w] = s;
}

__global__ void zero_kernel(float* __restrict__ p, int n) {
  int i = blockIdx.x * blockDim.x + threadIdx.x;
  if (i < n) p[i] = 0.f;
}

__global__ void tobf16_kernel(const float* __restrict__ in,
                              __nv_bfloat16* __restrict__ out, int n4) {
  int i = blockIdx.x * blockDim.x + threadIdx.x;
  if (i < n4) {
    float4 v = ((const float4*)in)[i];
    __nv_bfloat162 a = __floats2bfloat162_rn(v.x, v.y);
    __nv_bfloat162 b = __floats2bfloat162_rn(v.z, v.w);
    ((uint2*)out)[i] = make_uint2(*(uint32_t*)&a, *(uint32_t*)&b);
  }
}

__device__ __forceinline__ unsigned long long packdk(float d, int k) {
  unsigned u = __float_as_uint(d);
  u = (u & 0x80000000u) ? ~u : (u | 0x80000000u);
  return ((unsigned long long)u << 32) | (unsigned)k;
}

// ------------- bf16 HMMA mma.sync helper ---------------------------------
__device__ __forceinline__ void mma16816(float* c, const uint32_t* a,
                                         const uint32_t* b) {
  asm volatile(
      "mma.sync.aligned.m16n8k16.row.col.f32.bf16.bf16.f32 "
      "{%0,%1,%2,%3}, {%4,%5,%6,%7}, {%8,%9}, {%0,%1,%2,%3};"
      : "+f"(c[0]), "+f"(c[1]), "+f"(c[2]), "+f"(c[3])
      : "r"(a[0]), "r"(a[1]), "r"(a[2]), "r"(a[3]), "r"(b[0]), "r"(b[1]));
}

// ------------- phase 1: approx cross GEMM on HMMA ------------------------
__global__ __launch_bounds__(256) void cross_mma_kernel(
    const __nv_bfloat16* __restrict__ zb, const __nv_bfloat16* __restrict__ cbb,
    __nv_bfloat16* __restrict__ capx) {
  __shared__ __align__(16) __nv_bfloat16 As[128][72];
  __shared__ __align__(16) __nv_bfloat16 Bs[128][72];
  int tid = threadIdx.x;
  int wid = tid >> 5, lane = tid & 31;
  int gid = lane >> 2, tig = lane & 3;
  int wm = wid & 1, wn = wid >> 1;
  int s = blockIdx.z, k0 = blockIdx.x << 7, b0 = blockIdx.y << 7;

  float acc[4][4][4];
#pragma unroll
  for (int mf = 0; mf < 4; mf++)
#pragma unroll
    for (int nf = 0; nf < 4; nf++)
#pragma unroll
      for (int q = 0; q < 4; q++) acc[mf][nf][q] = 0.f;

  for (int kc = 0; kc < 4; kc++) {
    int koff = kc * 64;
    __syncthreads();
#pragma unroll
    for (int l = 0; l < 4; l++) {
      int idx = tid + l * 256;
      int r = idx >> 3, c8 = idx & 7;
      uint4 va = *(const uint4*)(zb + (size_t)(b0 + r) * SD + s * DD + koff + c8 * 8);
      *(uint4*)&As[r][c8 * 8] = va;
      uint4 vb = *(const uint4*)(cbb + ((size_t)s * KK + k0 + r) * DD + koff + c8 * 8);
      *(uint4*)&Bs[r][c8 * 8] = vb;
    }
    __syncthreads();

#pragma unroll
    for (int kk = 0; kk < 4; kk++) {
      int k16 = kk * 16;
      uint32_t a[4][4];
#pragma unroll
      for (int mf = 0; mf < 4; mf++) {
        int R = wm * 64 + mf * 16;
        a[mf][0] = *(const uint32_t*)&As[R + gid][k16 + 2 * tig];
        a[mf][1] = *(const uint32_t*)&As[R + gid + 8][k16 + 2 * tig];
        a[mf][2] = *(const uint32_t*)&As[R + gid][k16 + 8 + 2 * tig];
        a[mf][3] = *(const uint32_t*)&As[R + gid + 8][k16 + 8 + 2 * tig];
      }
#pragma unroll
      for (int nf = 0; nf < 4; nf++) {
        int C = wn * 32 + nf * 8;
        uint32_t b[2];
        b[0] = *(const uint32_t*)&Bs[C + gid][k16 + 2 * tig];
        b[1] = *(const uint32_t*)&Bs[C + gid][k16 + 8 + 2 * tig];
#pragma unroll
        for (int mf = 0; mf < 4; mf++) mma16816(acc[mf][nf], a[mf], b);
      }
    }
  }

#pragma unroll
  for (int mf = 0; mf < 4; mf++) {
    int row0 = wm * 64 + mf * 16 + gid;
#pragma unroll
    for (int nf = 0; nf < 4; nf++) {
      int col = k0 + wn * 32 + nf * 8 + 2 * tig;
      __nv_bfloat162 lo = __floats2bfloat162_rn(acc[mf][nf][0], acc[mf][nf][1]);
      __nv_bfloat162 hi = __floats2bfloat162_rn(acc[mf][nf][2], acc[mf][nf][3]);
      size_t g0 = ((size_t)s * BB + b0 + row0) * KK + col;
      size_t g1 = ((size_t)s * BB + b0 + row0 + 8) * KK + col;
      *(uint32_t*)(capx + g0) = *(uint32_t*)&lo;
      *(uint32_t*)(capx + g1) = *(uint32_t*)&hi;
    }
  }
}

// ------------- phase 2: scan + exact recheck of candidates ---------------
__global__ __launch_bounds__(256) void scan_kernel(
    const float* __restrict__ z, const float* __restrict__ cb,
    const __nv_bfloat16* __restrict__ capx, const float* __restrict__ zsq,
    const float* __restrict__ esq, int* __restrict__ codes,
    int* __restrict__ flags) {
  __shared__ __align__(16) __nv_bfloat16 crow[KK];
  __shared__ float zrow[DD];
  __shared__ float redf[8];
  __shared__ float bmax;
  __shared__ int cnt;
  __shared__ int cand[CAP];
  __shared__ unsigned long long packs[CAP];
  int srow = blockIdx.x;
  int s = srow >> 12, b = srow & 4095;
  int tid = threadIdx.x;
  const uint4* src = (const uint4*)(capx + (size_t)srow * KK);
  uint4* dc = (uint4*)crow;
#pragma unroll
  for (int l = 0; l < 4; l++) dc[tid + l * 256] = src[tid + l * 256];
  zrow[tid] = z[(size_t)b * SD + s * DD + tid];
  if (tid == 0) cnt = 0;
  __syncthreads();

  float mx = -1e30f;
#pragma unroll
  for (int l = 0; l < 32; l++)
    mx = fmaxf(mx, __bfloat162float(crow[tid + l * 256]));
#pragma unroll
  for (int o = 16; o; o >>= 1) mx = fmaxf(mx, __shfl_xor_sync(~0u, mx, o));
  if ((tid & 31) == 0) redf[tid >> 5] = mx;
  __syncthreads();
  if (tid == 0) {
    float m = redf[0];
#pragma unroll
    for (int i = 1; i < 8; i++) m = fmaxf(m, redf[i]);
    bmax = m;
  }
  __syncthreads();
  float th = bmax - MARGIN;
#pragma unroll
  for (int l = 0; l < 32; l++) {
    int k = tid + l * 256;
    if (__bfloat162float(crow[k]) >= th) {
      int p = atomicAdd(&cnt, 1);
      if (p < CAP) cand[p] = k;
    }
  }
  __syncthreads();
  int n = cnt;
  if (tid == 0) flags[srow] = (n > CAP) ? 1 : 0;
  if (n > CAP) return;

  if (tid < n) {
    int k = cand[tid];
    const float* e = cb + ((size_t)s * KK + k) * DD;
    float acc = 0.f;
#pragma unroll 8
    for (int d = 0; d < DD; d += 4) {
      float4 ev = *(const float4*)(e + d);
      acc = fmaf(zrow[d + 0], ev.x, acc);
      acc = fmaf(zrow[d + 1], ev.y, acc);
      acc = fmaf(zrow[d + 2], ev.z, acc);
      acc = fmaf(zrow[d + 3], ev.w, acc);
    }
    float t = zsq[b * SS + s] + esq[s * KK + k];
    float dv = t - 2.0f * acc;
    packs[tid] = packdk(dv, k);
  }
  __syncthreads();
  if (tid == 0) {
    unsigned long long m = packs[0];
    for (int i = 1; i < n; i++) { unsigned long long v = packs[i]; if (v < m) m = v; }
    codes[b * SS + s] = (int)(m & 0xffffffffULL);
  }
}

// ------------- fallback: full exact scan for overflowed rows -------------
__global__ __launch_bounds__(256) void fallback_kernel(
    const float* __restrict__ z, const float* __restrict__ cb,
    const float* __restrict__ zsq, const float* __restrict__ esq,
    int* __restrict__ codes, const int* __restrict__ flags) {
  if (!flags[blockIdx.x]) return;
  __shared__ float zrow[DD];
  __shared__ unsigned long long red[256];
  int srow = blockIdx.x;
  int s = srow >> 12, b = srow & 4095;
  int tid = threadIdx.x;
  zrow[tid] = z[(size_t)b * SD + s * DD + tid];
  __syncthreads();
  float zsqv = zsq[b * SS + s];
  unsigned long long best = ~0ull;
  for (int j = 0; j < 32; j++) {
    int k = tid + j * 256;
    const float* e = cb + ((size_t)s * KK + k) * DD;
    float acc = 0.f;
#pragma unroll 8
    for (int d = 0; d < DD; d += 4) {
      float4 ev = *(const float4*)(e + d);
      acc = fmaf(zrow[d + 0], ev.x, acc);
      acc = fmaf(zrow[d + 1], ev.y, acc);
      acc = fmaf(zrow[d + 2], ev.z, acc);
      acc = fmaf(zrow[d + 3], ev.w, acc);
    }
    float dv = (zsqv + esq[s * KK + k]) - 2.0f * acc;
    unsigned long long p = packdk(dv, k);
    if (p < best) best = p;
  }
  red[tid] = best;
  __syncthreads();
  for (int o = 128; o; o >>= 1) {
    if (tid < o) { unsigned long long v = red[tid + o]; if (v < red[tid]) red[tid] = v; }
    __syncthreads();
  }
  if (tid == 0) codes[b * SS + s] = (int)(red[0] & 0xffffffffULL);
}

// ------------- tail kernels ----------------------------------------------
__global__ void gather_kernel(const float* __restrict__ cb,
                              const int* __restrict__ codes,
                              float* __restrict__ quant) {
  int i = blockIdx.x * blockDim.x + threadIdx.x;
  int b = i >> 9, rem = i & 511;
  int s = rem >> 6, d4 = rem & 63;
  int code = codes[b * SS + s];
  float4 v = *(const float4*)(cb + ((size_t)(s * KK + code)) * DD + (d4 << 2));
  *(float4*)(quant + (size_t)b * SD + s * DD + (d4 << 2)) = v;
}

__global__ void count_kernel(const int* __restrict__ codes,
                             float* __restrict__ counts) {
  int i = blockIdx.x * blockDim.x + threadIdx.x;
  if (i < BB * SS) {
    int s = i & 7;
    atomicAdd(&counts[s * KK + codes[i]], 1.0f);
  }
}

__global__ void perp_kernel(const float* __restrict__ counts,
                            float* __restrict__ outp) {
  __shared__ float sh[256];
  __shared__ float perps;
  int tid = threadIdx.x;
  if (tid == 0) perps = 0.f;
  for (int s = 0; s < SS; s++) {
    float local = 0.f;
    for (int k = tid; k < KK; k += 256) {
      float p = counts[s * KK + k] * (1.0f / BB);
      local += p * logf(p + 1e-10f);
    }
    sh[tid] = local;
    __syncthreads();
    for (int o = 128; o; o >>= 1) {
      if (tid < o) sh[tid] += sh[tid + o];
      __syncthreads();
    }
    if (tid == 0) perps += expf(-sh[0]);
    __syncthreads();
  }
  if (tid == 0) *outp = perps * (1.0f / SS);
}

__global__ void copy4_kernel(float* __restrict__ dst,
                             const float* __restrict__ src, int n4) {
  int i = blockIdx.x * blockDim.x + threadIdx.x;
  if (i < n4) ((float4*)dst)[i] = ((const float4*)src)[i];
}

__global__ void codesf_kernel(float* __restrict__ dst,
                              const int* __restrict__ codes, int n) {
  int i = blockIdx.x * blockDim.x + threadIdx.x;
  if (i < n) dst[i] = (float)codes[i];
}

// --------------------------------------------------------------------------
extern "C" void kernel_launch(void* const* d_in, const int* in_sizes, int n_in,
                              void* d_out, int out_size) {
  const float* x     = (const float*)d_in[0];
  const float* enc_w = (const float*)d_in[1];
  const float* enc_b = (const float*)d_in[2];
  const float* cb    = (const float*)d_in[3];
  const float* dec_w = (const float*)d_in[4];
  const float* dec_b = (const float*)d_in[5];

  float *z, *quant, *recon, *zsq, *esq, *counts;
  int *codes, *flags;
  __nv_bfloat16 *zb, *cbb, *capx;
  __half *dwh, *dwl, *qh, *ql;
  cudaGetSymbolAddress((void**)&z, g_z);
  cudaGetSymbolAddress((void**)&quant, g_quant);
  cudaGetSymbolAddress((void**)&recon, g_recon);
  cudaGetSymbolAddress((void**)&zsq, g_zsq);
  cudaGetSymbolAddress((void**)&esq, g_esq);
  cudaGetSymbolAddress((void**)&counts, g_counts);
  cudaGetSymbolAddress((void**)&codes, g_codes);
  cudaGetSymbolAddress((void**)&flags, g_flags);
  cudaGetSymbolAddress((void**)&zb, g_zb);
  cudaGetSymbolAddress((void**)&cbb, g_cbb);
  cudaGetSymbolAddress((void**)&capx, g_capx);
  cudaGetSymbolAddress((void**)&dwh, g_dwh);
  cudaGetSymbolAddress((void**)&dwl, g_dwl);
  cudaGetSymbolAddress((void**)&qh, g_qh);
  cudaGetSymbolAddress((void**)&ql, g_ql);

  const int offQ = BB * IND;
  const int offC = offQ + BB * SD;
  const int offP = offC + BB * SS;
  float* out = (float*)d_out;
  float* reconDst = (out_size >= offQ) ? out : recon;

  // 1. encoder (fp32x2 packed FFMA, bit-identical chain): z = x@enc_w^T+b
  gemm128x2<<<dim3(SD / 128, BB / 128), 256>>>(x, enc_w, enc_b, z,
                                               BB, SD, IND);
  // 2. norms (unchanged reduction order)
  rowsq_kernel<<<BB * SS / 8, 256>>>(z, zsq, BB * SS);
  rowsq_kernel<<<SS * KK / 8, 256>>>(cb, esq, SS * KK);
  // 3. bf16 conversions for filter
  tobf16_kernel<<<BB * SD / 4 / 256, 256>>>(z, zb, BB * SD / 4);
  tobf16_kernel<<<SS * KK * DD / 4 / 256, 256>>>(cb, cbb, SS * KK * DD / 4);
  // 4. approx cross on HMMA tensor cores
  cross_mma_kernel<<<dim3(KK / 128, BB / 128, SS), 256>>>(zb, cbb, capx);
  // 5. scan + exact candidate recheck
  scan_kernel<<<BB * SS, 256>>>(z, cb, capx, zsq, esq, codes, flags);
  fallback_kernel<<<BB * SS, 256>>>(z, cb, zsq, esq, codes, flags);
  // 6. gather + counts
  gather_kernel<<<BB * SD / 4 / 256, 256>>>(cb, codes, quant);
  zero_kernel<<<SS * KK / 256, 256>>>(counts, SS * KK);
  count_kernel<<<BB * SS / 256, 256>>>(codes, counts);
  // 7. decoder (scaled fp16x3 tensor cores): x_recon = quant@dec_w^T + b
  split_kernel<<<IND * SD / 4 / 256, 256>>>(dec_w, dwh, dwl, 32.f,
                                            IND * SD / 4);
  split_kernel<<<BB * SD / 4 / 256, 256>>>(quant, qh, ql, 8192.f,
                                           BB * SD / 4);
  gemm3h<<<dim3(IND / 128, BB / 128), 256>>>(qh, ql, dwh, dwl, dec_b, reconDst,
                                             1.f / (8192.f * 32.f),
                                             BB, IND, SD);
  // 8. tuple tail
  if (out_size >= offC)
    copy4_kernel<<<BB * SD / 4 / 256, 256>>>(out + offQ, quant, BB * SD / 4);
  if (out_size >= offP)
    codesf_kernel<<<BB * SS / 256, 256>>>(out + offC, codes, BB * SS);
  if (out_size >= offP + 1)
    perp_kernel<<<1, 256>>>(counts, out + offP);
}

// round 13
// speedup vs baseline: 3.3394x; 1.0331x over previous
#include <cuda_runtime.h>
#include <cuda_bf16.h>
#include <cuda_fp16.h>
#include <math.h>
#include <stdint.h>

#define BB 4096
#define IND 2048
#define SS 8
#define DD 256
#define KK 8192
#define SD 2048   // S*D

#define CAP 96
#define MARGIN 2e-4f

// ------------- device-global scratch -------------------------------------
__device__ float g_z[(size_t)BB * SD];
__device__ float g_quant[(size_t)BB * SD];
__device__ float g_recon[(size_t)BB * IND];
__device__ float g_zsq[BB * SS];
__device__ float g_esq[SS * KK];
__device__ int   g_codes[BB * SS];
__device__ float g_counts[SS * KK];
__device__ int   g_flags[BB * SS];
__device__ __nv_bfloat16 g_zb[(size_t)BB * SD];
__device__ __nv_bfloat16 g_cbb[(size_t)SS * KK * DD];
__device__ __nv_bfloat16 g_capx[(size_t)BB * SS * KK];   // approx cross
// fp16 split operands (decoder only — encoder must stay bit-exact fp32)
__device__ __half g_dwh[(size_t)IND * SD];
__device__ __half g_dwl[(size_t)IND * SD];
__device__ __half g_qh[(size_t)BB * SD];
__device__ __half g_ql[(size_t)BB * SD];

// ------------- f32x2 packed-FMA helpers ----------------------------------
__device__ __forceinline__ unsigned long long pk2(float x, float y) {
  unsigned long long r;
  asm("mov.b64 %0, {%1, %2};" : "=l"(r) : "f"(x), "f"(y));
  return r;
}
__device__ __forceinline__ void fma2(unsigned long long& d,
                                     unsigned long long a,
                                     unsigned long long b) {
  asm("fma.rn.f32x2 %0, %1, %2, %0;" : "+l"(d) : "l"(a), "l"(b));
}
__device__ __forceinline__ void upk2(float& x, float& y,
                                     unsigned long long a) {
  asm("mov.b64 {%0, %1}, %2;" : "=f"(x), "=f"(y) : "l"(a));
}

// ------------- fp32 GEMM via packed f32x2 FFMA (conflict-free layout) ----
// Bit-identical per-output k-sequential FMA chain to the proven gemm_nt.
// grid (N/128, M/128); block 256; 8x8 outputs/thread in 2x2 float4 segs.
__global__ __launch_bounds__(256) void gemm128x2(
    const float* __restrict__ A, const float* __restrict__ Wt,
    const float* __restrict__ bias, float* __restrict__ C, int M, int N,
    int Kd) {
  __shared__ __align__(16) float xs[16][132];
  __shared__ __align__(16) float ws[16][132];
  int tid = threadIdx.x;
  int ty = tid >> 4, tx = tid & 15;
  int row0 = blockIdx.y << 7, col0 = blockIdx.x << 7;
  int lrow = tid >> 1, lk8 = (tid & 1) << 3;

  unsigned long long acc[8][4];
#pragma unroll
  for (int i = 0; i < 8; i++)
#pragma unroll
    for (int j = 0; j < 4; j++) acc[i][j] = 0ull;

  for (int k0 = 0; k0 < Kd; k0 += 16) {
    float4 a0 = *(const float4*)(A + (size_t)(row0 + lrow) * Kd + k0 + lk8);
    float4 a1 = *(const float4*)(A + (size_t)(row0 + lrow) * Kd + k0 + lk8 + 4);
    float4 b0 = *(const float4*)(Wt + (size_t)(col0 + lrow) * Kd + k0 + lk8);
    float4 b1 = *(const float4*)(Wt + (size_t)(col0 + lrow) * Kd + k0 + lk8 + 4);
    __syncthreads();
    xs[lk8 + 0][lrow] = a0.x; xs[lk8 + 1][lrow] = a0.y;
    xs[lk8 + 2][lrow] = a0.z; xs[lk8 + 3][lrow] = a0.w;
    xs[lk8 + 4][lrow] = a1.x; xs[lk8 + 5][lrow] = a1.y;
    xs[lk8 + 6][lrow] = a1.z; xs[lk8 + 7][lrow] = a1.w;
    ws[lk8 + 0][lrow] = b0.x; ws[lk8 + 1][lrow] = b0.y;
    ws[lk8 + 2][lrow] = b0.z; ws[lk8 + 3][lrow] = b0.w;
    ws[lk8 + 4][lrow] = b1.x; ws[lk8 + 5][lrow] = b1.y;
    ws[lk8 + 6][lrow] = b1.z; ws[lk8 + 7][lrow] = b1.w;
    __syncthreads();
#pragma unroll
    for (int kk = 0; kk < 16; kk++) {
      // rows: ty*4..+3 and 64+ty*4..+3  (xs phase = broadcast)
      float4 av0 = *(const float4*)&xs[kk][ty << 2];
      float4 av1 = *(const float4*)&xs[kk][64 + (ty << 2)];
      // cols: tx*4..+3 and 64+tx*4..+3  (ws phase = banks 4tx..4tx+3, CF)
      float4 bv0 = *(const float4*)&ws[kk][tx << 2];
      float4 bv1 = *(const float4*)&ws[kk][64 + (tx << 2)];
      unsigned long long b2[4];
      b2[0] = pk2(bv0.x, bv0.y); b2[1] = pk2(bv0.z, bv0.w);
      b2[2] = pk2(bv1.x, bv1.y); b2[3] = pk2(bv1.z, bv1.w);
      float ar[8] = {av0.x, av0.y, av0.z, av0.w, av1.x, av1.y, av1.z, av1.w};
#pragma unroll
      for (int i = 0; i < 8; i++) {
        unsigned long long a2 = pk2(ar[i], ar[i]);
#pragma unroll
        for (int j = 0; j < 4; j++) fma2(acc[i][j], a2, b2[j]);
      }
    }
  }
#pragma unroll
  for (int i = 0; i < 8; i++) {
    int r = row0 + ((i < 4) ? ((ty << 2) + i) : (64 + (ty << 2) + i - 4));
    int c0 = col0 + (tx << 2);
    int c1 = col0 + 64 + (tx << 2);
    float o[8];
#pragma unroll
    for (int j = 0; j < 4; j++) upk2(o[2 * j], o[2 * j + 1], acc[i][j]);
    *(float4*)(C + (size_t)r * N + c0) =
        make_float4(o[0] + bias[c0], o[1] + bias[c0 + 1],
                    o[2] + bias[c0 + 2], o[3] + bias[c0 + 3]);
    *(float4*)(C + (size_t)r * N + c1) =
        make_float4(o[4] + bias[c1], o[5] + bias[c1 + 1],
                    o[6] + bias[c1 + 2], o[7] + bias[c1 + 3]);
  }
}

// ------------- split fp32 -> fp16 hi/lo with exact pow2 pre-scale --------
__global__ void split_kernel(const float* __restrict__ in,
                             __half* __restrict__ hi, __half* __restrict__ lo,
                             float scale, int n4) {
  int i = blockIdx.x * blockDim.x + threadIdx.x;
  if (i < n4) {
    float4 v = ((const float4*)in)[i];
    v.x *= scale; v.y *= scale; v.z *= scale; v.w *= scale;
    __half hx = __float2half_rn(v.x), hy = __float2half_rn(v.y);
    __half hz = __float2half_rn(v.z), hw = __float2half_rn(v.w);
    __half lx = __float2half_rn(v.x - __half2float(hx));
    __half ly = __float2half_rn(v.y - __half2float(hy));
    __half lz = __float2half_rn(v.z - __half2float(hz));
    __half lw = __float2half_rn(v.w - __half2float(hw));
    __half2 h0 = __halves2half2(hx, hy), h1 = __halves2half2(hz, hw);
    __half2 l0 = __halves2half2(lx, ly), l1 = __halves2half2(lz, lw);
    ((uint2*)hi)[i] = make_uint2(*(uint32_t*)&h0, *(uint32_t*)&h1);
    ((uint2*)lo)[i] = make_uint2(*(uint32_t*)&l0, *(uint32_t*)&l1);
  }
}

// ------------- fp16 mma helper -------------------------------------------
__device__ __forceinline__ void mmaf16(float* c, const uint32_t* a,
                                       const uint32_t* b) {
  asm volatile(
      "mma.sync.aligned.m16n8k16.row.col.f32.f16.f16.f32 "
      "{%0,%1,%2,%3}, {%4,%5,%6,%7}, {%8,%9}, {%0,%1,%2,%3};"
      : "+f"(c[0]), "+f"(c[1]), "+f"(c[2]), "+f"(c[3])
      : "r"(a[0]), "r"(a[1]), "r"(a[2]), "r"(a[3]), "r"(b[0]), "r"(b[1]));
}

// ------------- 3-product fp16-split GEMM (decoder): C = inv*(A@W^T)+b ----
__global__ __launch_bounds__(256) void gemm3h(
    const __half* __restrict__ Ah, const __half* __restrict__ Al,
    const __half* __restrict__ Wh, const __half* __restrict__ Wl,
    const float* __restrict__ bias, float* __restrict__ C, float inv, int M,
    int N, int Kd) {
  __shared__ __align__(16) __half Ahs[128][40];
  __shared__ __align__(16) __half Als[128][40];
  __shared__ __align__(16) __half Whs[128][40];
  __shared__ __align__(16) __half Wls[128][40];
  int tid = threadIdx.x;
  int wid = tid >> 5, lane = tid & 31;
  int gid = lane >> 2, tig = lane & 3;
  int wm = wid & 1, wn = wid >> 1;
  int row0 = blockIdx.y << 7, col0 = blockIdx.x << 7;

  float acc[4][4][4];
#pragma unroll
  for (int mf = 0; mf < 4; mf++)
#pragma unroll
    for (int nf = 0; nf < 4; nf++)
#pragma unroll
      for (int q = 0; q < 4; q++) acc[mf][nf][q] = 0.f;

  for (int k0 = 0; k0 < Kd; k0 += 32) {
    __syncthreads();
#pragma unroll
    for (int l = 0; l < 2; l++) {
      int idx = tid + l * 256;
      int r = idx >> 2, c8 = (idx & 3) * 8;
      size_t ga = (size_t)(row0 + r) * Kd + k0 + c8;
      size_t gw = (size_t)(col0 + r) * Kd + k0 + c8;
      *(uint4*)&Ahs[r][c8] = *(const uint4*)(Ah + ga);
      *(uint4*)&Als[r][c8] = *(const uint4*)(Al + ga);
      *(uint4*)&Whs[r][c8] = *(const uint4*)(Wh + gw);
      *(uint4*)&Wls[r][c8] = *(const uint4*)(Wl + gw);
    }
    __syncthreads();

#pragma unroll
    for (int kk = 0; kk < 2; kk++) {
      int k16 = kk * 16;
      uint32_t ah[4][4], al[4][4];
#pragma unroll
      for (int mf = 0; mf < 4; mf++) {
        int R = wm * 64 + mf * 16;
        ah[mf][0] = *(const uint32_t*)&Ahs[R + gid][k16 + 2 * tig];
        ah[mf][1] = *(const uint32_t*)&Ahs[R + gid + 8][k16 + 2 * tig];
        ah[mf][2] = *(const uint32_t*)&Ahs[R + gid][k16 + 8 + 2 * tig];
        ah[mf][3] = *(const uint32_t*)&Ahs[R + gid + 8][k16 + 8 + 2 * tig];
        al[mf][0] = *(const uint32_t*)&Als[R + gid][k16 + 2 * tig];
        al[mf][1] = *(const uint32_t*)&Als[R + gid + 8][k16 + 2 * tig];
        al[mf][2] = *(const uint32_t*)&Als[R + gid][k16 + 8 + 2 * tig];
        al[mf][3] = *(const uint32_t*)&Als[R + gid + 8][k16 + 8 + 2 * tig];
      }
#pragma unroll
      for (int nf = 0; nf < 4; nf++) {
        int Cc = wn * 32 + nf * 8;
        uint32_t bh[2], bl[2];
        bh[0] = *(const uint32_t*)&Whs[Cc + gid][k16 + 2 * tig];
        bh[1] = *(const uint32_t*)&Whs[Cc + gid][k16 + 8 + 2 * tig];
        bl[0] = *(const uint32_t*)&Wls[Cc + gid][k16 + 2 * tig];
        bl[1] = *(const uint32_t*)&Wls[Cc + gid][k16 + 8 + 2 * tig];
#pragma unroll
        for (int mf = 0; mf < 4; mf++) {
          mmaf16(acc[mf][nf], ah[mf], bh);
          mmaf16(acc[mf][nf], ah[mf], bl);
          mmaf16(acc[mf][nf], al[mf], bh);
        }
      }
    }
  }

#pragma unroll
  for (int mf = 0; mf < 4; mf++) {
    int r0 = row0 + wm * 64 + mf * 16 + gid;
#pragma unroll
    for (int nf = 0; nf < 4; nf++) {
      int c = col0 + wn * 32 + nf * 8 + 2 * tig;
      float b0 = bias[c], b1 = bias[c + 1];
      float2 lo = make_float2(acc[mf][nf][0] * inv + b0,
                              acc[mf][nf][1] * inv + b1);
      float2 hi = make_float2(acc[mf][nf][2] * inv + b0,
                              acc[mf][nf][3] * inv + b1);
      *(float2*)(C + (size_t)r0 * N + c) = lo;
      *(float2*)(C + (size_t)(r0 + 8) * N + c) = hi;
    }
  }
}

// ------------- row sum-of-squares (order is load-bearing) ----------------
__global__ void rowsq_kernel(const float* __restrict__ in,
                             float* __restrict__ out, int nrows) {
  int w = (blockIdx.x * blockDim.x + threadIdx.x) >> 5;
  int lane = threadIdx.x & 31;
  if (w >= nrows) return;
  const float* p = in + (size_t)w * DD;
  float s = 0.f;
#pragma unroll
  for (int i = 0; i < 8; i++) { float v = p[lane + 32 * i]; s += v * v; }
#pragma unroll
  for (int o = 16; o; o >>= 1) s += __shfl_xor_sync(0xffffffffu, s, o);
  if (lane == 0) out[w] = s;
}

__global__ void zero_kernel(float* __restrict__ p, int n) {
  int i = blockIdx.x * blockDim.x + threadIdx.x;
  if (i < n) p[i] = 0.f;
}

__global__ void tobf16_kernel(const float* __restrict__ in,
                              __nv_bfloat16* __restrict__ out, int n4) {
  int i = blockIdx.x * blockDim.x + threadIdx.x;
  if (i < n4) {
    float4 v = ((const float4*)in)[i];
    __nv_bfloat162 a = __floats2bfloat162_rn(v.x, v.y);
    __nv_bfloat162 b = __floats2bfloat162_rn(v.z, v.w);
    ((uint2*)out)[i] = make_uint2(*(uint32_t*)&a, *(uint32_t*)&b);
  }
}

__device__ __forceinline__ unsigned long long packdk(float d, int k) {
  unsigned u = __float_as_uint(d);
  u = (u & 0x80000000u) ? ~u : (u | 0x80000000u);
  return ((unsigned long long)u << 32) | (unsigned)k;
}

// ------------- bf16 HMMA mma.sync helper ---------------------------------
__device__ __forceinline__ void mma16816(float* c, const uint32_t* a,
                                         const uint32_t* b) {
  asm volatile(
      "mma.sync.aligned.m16n8k16.row.col.f32.bf16.bf16.f32 "
      "{%0,%1,%2,%3}, {%4,%5,%6,%7}, {%8,%9}, {%0,%1,%2,%3};"
      : "+f"(c[0]), "+f"(c[1]), "+f"(c[2]), "+f"(c[3])
      : "r"(a[0]), "r"(a[1]), "r"(a[2]), "r"(a[3]), "r"(b[0]), "r"(b[1]));
}

// ------------- phase 1: approx cross GEMM on HMMA ------------------------
__global__ __launch_bounds__(256) void cross_mma_kernel(
    const __nv_bfloat16* __restrict__ zb, const __nv_bfloat16* __restrict__ cbb,
    __nv_bfloat16* __restrict__ capx) {
  __shared__ __align__(16) __nv_bfloat16 As[128][72];
  __shared__ __align__(16) __nv_bfloat16 Bs[128][72];
  int tid = threadIdx.x;
  int wid = tid >> 5, lane = tid & 31;
  int gid = lane >> 2, tig = lane & 3;
  int wm = wid & 1, wn = wid >> 1;
  int s = blockIdx.z, k0 = blockIdx.x << 7, b0 = blockIdx.y << 7;

  float acc[4][4][4];
#pragma unroll
  for (int mf = 0; mf < 4; mf++)
#pragma unroll
    for (int nf = 0; nf < 4; nf++)
#pragma unroll
      for (int q = 0; q < 4; q++) acc[mf][nf][q] = 0.f;

  for (int kc = 0; kc < 4; kc++) {
    int koff = kc * 64;
    __syncthreads();
#pragma unroll
    for (int l = 0; l < 4; l++) {
      int idx = tid + l * 256;
      int r = idx >> 3, c8 = idx & 7;
      uint4 va = *(const uint4*)(zb + (size_t)(b0 + r) * SD + s * DD + koff + c8 * 8);
      *(uint4*)&As[r][c8 * 8] = va;
      uint4 vb = *(const uint4*)(cbb + ((size_t)s * KK + k0 + r) * DD + koff + c8 * 8);
      *(uint4*)&Bs[r][c8 * 8] = vb;
    }
    __syncthreads();

#pragma unroll
    for (int kk = 0; kk < 4; kk++) {
      int k16 = kk * 16;
      uint32_t a[4][4];
#pragma unroll
      for (int mf = 0; mf < 4; mf++) {
        int R = wm * 64 + mf * 16;
        a[mf][0] = *(const uint32_t*)&As[R + gid][k16 + 2 * tig];
        a[mf][1] = *(const uint32_t*)&As[R + gid + 8][k16 + 2 * tig];
        a[mf][2] = *(const uint32_t*)&As[R + gid][k16 + 8 + 2 * tig];
        a[mf][3] = *(const uint32_t*)&As[R + gid + 8][k16 + 8 + 2 * tig];
      }
#pragma unroll
      for (int nf = 0; nf < 4; nf++) {
        int C = wn * 32 + nf * 8;
        uint32_t b[2];
        b[0] = *(const uint32_t*)&Bs[C + gid][k16 + 2 * tig];
        b[1] = *(const uint32_t*)&Bs[C + gid][k16 + 8 + 2 * tig];
#pragma unroll
        for (int mf = 0; mf < 4; mf++) mma16816(acc[mf][nf], a[mf], b);
      }
    }
  }

#pragma unroll
  for (int mf = 0; mf < 4; mf++) {
    int row0 = wm * 64 + mf * 16 + gid;
#pragma unroll
    for (int nf = 0; nf < 4; nf++) {
      int col = k0 + wn * 32 + nf * 8 + 2 * tig;
      __nv_bfloat162 lo = __floats2bfloat162_rn(acc[mf][nf][0], acc[mf][nf][1]);
      __nv_bfloat162 hi = __floats2bfloat162_rn(acc[mf][nf][2], acc[mf][nf][3]);
      size_t g0 = ((size_t)s * BB + b0 + row0) * KK + col;
      size_t g1 = ((size_t)s * BB + b0 + row0 + 8) * KK + col;
      *(uint32_t*)(capx + g0) = *(uint32_t*)&lo;
      *(uint32_t*)(capx + g1) = *(uint32_t*)&hi;
    }
  }
}

// ------------- phase 2: scan + exact recheck of candidates ---------------
__global__ __launch_bounds__(256) void scan_kernel(
    const float* __restrict__ z, const float* __restrict__ cb,
    const __nv_bfloat16* __restrict__ capx, const float* __restrict__ zsq,
    const float* __restrict__ esq, int* __restrict__ codes,
    int* __restrict__ flags) {
  __shared__ __align__(16) __nv_bfloat16 crow[KK];
  __shared__ float zrow[DD];
  __shared__ float redf[8];
  __shared__ float bmax;
  __shared__ int cnt;
  __shared__ int cand[CAP];
  __shared__ unsigned long long packs[CAP];
  int srow = blockIdx.x;
  int s = srow >> 12, b = srow & 4095;
  int tid = threadIdx.x;
  const uint4* src = (const uint4*)(capx + (size_t)srow * KK);
  uint4* dc = (uint4*)crow;
#pragma unroll
  for (int l = 0; l < 4; l++) dc[tid + l * 256] = src[tid + l * 256];
  zrow[tid] = z[(size_t)b * SD + s * DD + tid];
  if (tid == 0) cnt = 0;
  __syncthreads();

  float mx = -1e30f;
#pragma unroll
  for (int l = 0; l < 32; l++)
    mx = fmaxf(mx, __bfloat162float(crow[tid + l * 256]));
#pragma unroll
  for (int o = 16; o; o >>= 1) mx = fmaxf(mx, __shfl_xor_sync(~0u, mx, o));
  if ((tid & 31) == 0) redf[tid >> 5] = mx;
  __syncthreads();
  if (tid == 0) {
    float m = redf[0];
#pragma unroll
    for (int i = 1; i < 8; i++) m = fmaxf(m, redf[i]);
    bmax = m;
  }
  __syncthreads();
  float th = bmax - MARGIN;
#pragma unroll
  for (int l = 0; l < 32; l++) {
    int k = tid + l * 256;
    if (__bfloat162float(crow[k]) >= th) {
      int p = atomicAdd(&cnt, 1);
      if (p < CAP) cand[p] = k;
    }
  }
  __syncthreads();
  int n = cnt;
  if (tid == 0) flags[srow] = (n > CAP) ? 1 : 0;
  if (n > CAP) return;

  if (tid < n) {
    int k = cand[tid];
    const float* e = cb + ((size_t)s * KK + k) * DD;
    float acc = 0.f;
#pragma unroll 8
    for (int d = 0; d < DD; d += 4) {
      float4 ev = *(const float4*)(e + d);
      acc = fmaf(zrow[d + 0], ev.x, acc);
      acc = fmaf(zrow[d + 1], ev.y, acc);
      acc = fmaf(zrow[d + 2], ev.z, acc);
      acc = fmaf(zrow[d + 3], ev.w, acc);
    }
    float t = zsq[b * SS + s] + esq[s * KK + k];
    float dv = t - 2.0f * acc;
    packs[tid] = packdk(dv, k);
  }
  __syncthreads();
  if (tid == 0) {
    unsigned long long m = packs[0];
    for (int i = 1; i < n; i++) { unsigned long long v = packs[i]; if (v < m) m = v; }
    codes[b * SS + s] = (int)(m & 0xffffffffULL);
  }
}

// ------------- fallback: full exact scan for overflowed rows -------------
__global__ __launch_bounds__(256) void fallback_kernel(
    const float* __restrict__ z, const float* __restrict__ cb,
    const float* __restrict__ zsq, const float* __restrict__ esq,
    int* __restrict__ codes, const int* __restrict__ flags) {
  if (!flags[blockIdx.x]) return;
  __shared__ float zrow[DD];
  __shared__ unsigned long long red[256];
  int srow = blockIdx.x;
  int s = srow >> 12, b = srow & 4095;
  int tid = threadIdx.x;
  zrow[tid] = z[(size_t)b * SD + s * DD + tid];
  __syncthreads();
  float zsqv = zsq[b * SS + s];
  unsigned long long best = ~0ull;
  for (int j = 0; j < 32; j++) {
    int k = tid + j * 256;
    const float* e = cb + ((size_t)s * KK + k) * DD;
    float acc = 0.f;
#pragma unroll 8
    for (int d = 0; d < DD; d += 4) {
      float4 ev = *(const float4*)(e + d);
      acc = fmaf(zrow[d + 0], ev.x, acc);
      acc = fmaf(zrow[d + 1], ev.y, acc);
      acc = fmaf(zrow[d + 2], ev.z, acc);
      acc = fmaf(zrow[d + 3], ev.w, acc);
    }
    float dv = (zsqv + esq[s * KK + k]) - 2.0f * acc;
    unsigned long long p = packdk(dv, k);
    if (p < best) best = p;
  }
  red[tid] = best;
  __syncthreads();
  for (int o = 128; o; o >>= 1) {
    if (tid < o) { unsigned long long v = red[tid + o]; if (v < red[tid]) red[tid] = v; }
    __syncthreads();
  }
  if (tid == 0) codes[b * SS + s] = (int)(red[0] & 0xffffffffULL);
}

// ------------- tail kernels ----------------------------------------------
__global__ void gather_kernel(const float* __restrict__ cb,
                              const int* __restrict__ codes,
                              float* __restrict__ quant) {
  int i = blockIdx.x * blockDim.x + threadIdx.x;
  int b = i >> 9, rem = i & 511;
  int s = rem >> 6, d4 = rem & 63;
  int code = codes[b * SS + s];
  float4 v = *(const float4*)(cb + ((size_t)(s * KK + code)) * DD + (d4 << 2));
  *(float4*)(quant + (size_t)b * SD + s * DD + (d4 << 2)) = v;
}

__global__ void count_kernel(const int* __restrict__ codes,
                             float* __restrict__ counts) {
  int i = blockIdx.x * blockDim.x + threadIdx.x;
  if (i < BB * SS) {
    int s = i & 7;
    atomicAdd(&counts[s * KK + codes[i]], 1.0f);
  }
}

__global__ void perp_kernel(const float* __restrict__ counts,
                            float* __restrict__ outp) {
  __shared__ float sh[256];
  __shared__ float perps;
  int tid = threadIdx.x;
  if (tid == 0) perps = 0.f;
  for (int s = 0; s < SS; s++) {
    float local = 0.f;
    for (int k = tid; k < KK; k += 256) {
      float p = counts[s * KK + k] * (1.0f / BB);
      local += p * logf(p + 1e-10f);
    }
    sh[tid] = local;
    __syncthreads();
    for (int o = 128; o; o >>= 1) {
      if (tid < o) sh[tid] += sh[tid + o];
      __syncthreads();
    }
    if (tid == 0) perps += expf(-sh[0]);
    __syncthreads();
  }
  if (tid == 0) *outp = perps * (1.0f / SS);
}

__global__ void copy4_kernel(float* __restrict__ dst,
                             const float* __restrict__ src, int n4) {
  int i = blockIdx.x * blockDim.x + threadIdx.x;
  if (i < n4) ((float4*)dst)[i] = ((const float4*)src)[i];
}

__global__ void codesf_kernel(float* __restrict__ dst,
                              const int* __restrict__ codes, int n) {
  int i = blockIdx.x * blockDim.x + threadIdx.x;
  if (i < n) dst[i] = (float)codes[i];
}

// --------------------------------------------------------------------------
extern "C" void kernel_launch(void* const* d_in, const int* in_sizes, int n_in,
                              void* d_out, int out_size) {
  const float* x     = (const float*)d_in[0];
  const float* enc_w = (const float*)d_in[1];
  const float* enc_b = (const float*)d_in[2];
  const float* cb    = (const float*)d_in[3];
  const float* dec_w = (const float*)d_in[4];
  const float* dec_b = (const float*)d_in[5];

  float *z, *quant, *recon, *zsq, *esq, *counts;
  int *codes, *flags;
  __nv_bfloat16 *zb, *cbb, *capx;
  __half *dwh, *dwl, *qh, *ql;
  cudaGetSymbolAddress((void**)&z, g_z);
  cudaGetSymbolAddress((void**)&quant, g_quant);
  cudaGetSymbolAddress((void**)&recon, g_recon);
  cudaGetSymbolAddress((void**)&zsq, g_zsq);
  cudaGetSymbolAddress((void**)&esq, g_esq);
  cudaGetSymbolAddress((void**)&counts, g_counts);
  cudaGetSymbolAddress((void**)&codes, g_codes);
  cudaGetSymbolAddress((void**)&flags, g_flags);
  cudaGetSymbolAddress((void**)&zb, g_zb);
  cudaGetSymbolAddress((void**)&cbb, g_cbb);
  cudaGetSymbolAddress((void**)&capx, g_capx);
  cudaGetSymbolAddress((void**)&dwh, g_dwh);
  cudaGetSymbolAddress((void**)&dwl, g_dwl);
  cudaGetSymbolAddress((void**)&qh, g_qh);
  cudaGetSymbolAddress((void**)&ql, g_ql);

  const int offQ = BB * IND;
  const int offC = offQ + BB * SD;
  const int offP = offC + BB * SS;
  float* out = (float*)d_out;
  float* reconDst = (out_size >= offQ) ? out : recon;

  // 1. encoder (fp32x2 packed FFMA, bit-identical chain, CF smem layout)
  gemm128x2<<<dim3(SD / 128, BB / 128), 256>>>(x, enc_w, enc_b, z,
                                               BB, SD, IND);
  // 2. norms (unchanged reduction order)
  rowsq_kernel<<<BB * SS / 8, 256>>>(z, zsq, BB * SS);
  rowsq_kernel<<<SS * KK / 8, 256>>>(cb, esq, SS * KK);
  // 3. bf16 conversions for filter
  tobf16_kernel<<<BB * SD / 4 / 256, 256>>>(z, zb, BB * SD / 4);
  tobf16_kernel<<<SS * KK * DD / 4 / 256, 256>>>(cb, cbb, SS * KK * DD / 4);
  // 4. approx cross on HMMA tensor cores
  cross_mma_kernel<<<dim3(KK / 128, BB / 128, SS), 256>>>(zb, cbb, capx);
  // 5. scan + exact candidate recheck
  scan_kernel<<<BB * SS, 256>>>(z, cb, capx, zsq, esq, codes, flags);
  fallback_kernel<<<BB * SS, 256>>>(z, cb, zsq, esq, codes, flags);
  // 6. gather + counts
  gather_kernel<<<BB * SD / 4 / 256, 256>>>(cb, codes, quant);
  zero_kernel<<<SS * KK / 256, 256>>>(counts, SS * KK);
  count_kernel<<<BB * SS / 256, 256>>>(codes, counts);
  // 7. decoder (scaled fp16x3 tensor cores): x_recon = quant@dec_w^T + b
  split_kernel<<<IND * SD / 4 / 256, 256>>>(dec_w, dwh, dwl, 32.f,
                                            IND * SD / 4);
  split_kernel<<<BB * SD / 4 / 256, 256>>>(quant, qh, ql, 8192.f,
                                           BB * SD / 4);
  gemm3h<<<dim3(IND / 128, BB / 128), 256>>>(qh, ql, dwh, dwl, dec_b, reconDst,
                                             1.f / (8192.f * 32.f),
                                             BB, IND, SD);
  // 8. tuple tail
  if (out_size >= offC)
    copy4_kernel<<<BB * SD / 4 / 256, 256>>>(out + offQ, quant, BB * SD / 4);
  if (out_size >= offP)
    codesf_kernel<<<BB * SS / 256, 256>>>(out + offC, codes, BB * SS);
  if (out_size >= offP + 1)
    perp_kernel<<<1, 256>>>(counts, out + offP);
}

// round 14
// speedup vs baseline: 3.4339x; 1.0283x over previous
#include <cuda_runtime.h>
#include <cuda_bf16.h>
#include <cuda_fp16.h>
#include <math.h>
#include <stdint.h>

#define BB 4096
#define IND 2048
#define SS 8
#define DD 256
#define KK 8192
#define SD 2048   // S*D

#define CAP 96
#define MARGIN 2e-4f

// ------------- device-global scratch -------------------------------------
__device__ float g_z[(size_t)BB * SD];
__device__ float g_quant[(size_t)BB * SD];
__device__ float g_recon[(size_t)BB * IND];
__device__ float g_zsq[BB * SS];
__device__ float g_esq[SS * KK];
__device__ int   g_codes[BB * SS];
__device__ float g_counts[SS * KK];
__device__ int   g_flags[BB * SS];
__device__ __nv_bfloat16 g_zb[(size_t)BB * SD];
__device__ __nv_bfloat16 g_cbb[(size_t)SS * KK * DD];
__device__ __nv_bfloat16 g_capx[(size_t)BB * SS * KK];   // approx cross
// fp16 split operands (decoder only — encoder must stay bit-exact fp32)
__device__ __half g_dwh[(size_t)IND * SD];
__device__ __half g_dwl[(size_t)IND * SD];
__device__ __half g_qh[(size_t)BB * SD];
__device__ __half g_ql[(size_t)BB * SD];

// ------------- f32x2 packed-FMA helpers ----------------------------------
__device__ __forceinline__ unsigned long long pk2(float x, float y) {
  unsigned long long r;
  asm("mov.b64 %0, {%1, %2};" : "=l"(r) : "f"(x), "f"(y));
  return r;
}
__device__ __forceinline__ void fma2(unsigned long long& d,
                                     unsigned long long a,
                                     unsigned long long b) {
  asm("fma.rn.f32x2 %0, %1, %2, %0;" : "+l"(d) : "l"(a), "l"(b));
}
__device__ __forceinline__ void upk2(float& x, float& y,
                                     unsigned long long a) {
  asm("mov.b64 {%0, %1}, %2;" : "=f"(x), "=f"(y) : "l"(a));
}

// ------------- fp32 GEMM, packed f32x2 FFMA, double-buffered smem --------
// Per-output k-sequential FMA chain bit-identical to R13 (FROZEN).
// grid (N/128, M/128); block 256; 8x8 outputs/thread in 2x2 float4 segs.
__global__ __launch_bounds__(256) void gemm128x2(
    const float* __restrict__ A, const float* __restrict__ Wt,
    const float* __restrict__ bias, float* __restrict__ C, int M, int N,
    int Kd) {
  __shared__ __align__(16) float xs[2][16][132];
  __shared__ __align__(16) float ws[2][16][132];
  int tid = threadIdx.x;
  int ty = tid >> 4, tx = tid & 15;
  int row0 = blockIdx.y << 7, col0 = blockIdx.x << 7;
  int lrow = tid >> 1, lk8 = (tid & 1) << 3;

  unsigned long long acc[8][4];
#pragma unroll
  for (int i = 0; i < 8; i++)
#pragma unroll
    for (int j = 0; j < 4; j++) acc[i][j] = 0ull;

  const float* Ap = A + (size_t)(row0 + lrow) * Kd + lk8;
  const float* Wp = Wt + (size_t)(col0 + lrow) * Kd + lk8;

  // prologue: chunk 0 -> buffer 0
  {
    float4 a0 = *(const float4*)(Ap);
    float4 a1 = *(const float4*)(Ap + 4);
    float4 b0 = *(const float4*)(Wp);
    float4 b1 = *(const float4*)(Wp + 4);
    xs[0][lk8 + 0][lrow] = a0.x; xs[0][lk8 + 1][lrow] = a0.y;
    xs[0][lk8 + 2][lrow] = a0.z; xs[0][lk8 + 3][lrow] = a0.w;
    xs[0][lk8 + 4][lrow] = a1.x; xs[0][lk8 + 5][lrow] = a1.y;
    xs[0][lk8 + 6][lrow] = a1.z; xs[0][lk8 + 7][lrow] = a1.w;
    ws[0][lk8 + 0][lrow] = b0.x; ws[0][lk8 + 1][lrow] = b0.y;
    ws[0][lk8 + 2][lrow] = b0.z; ws[0][lk8 + 3][lrow] = b0.w;
    ws[0][lk8 + 4][lrow] = b1.x; ws[0][lk8 + 5][lrow] = b1.y;
    ws[0][lk8 + 6][lrow] = b1.z; ws[0][lk8 + 7][lrow] = b1.w;
  }
  __syncthreads();

  int NC = Kd >> 4;
  for (int ch = 0; ch < NC; ch++) {
    int cur = ch & 1, nxt = cur ^ 1;
    float4 a0, a1, b0, b1;
    bool more = (ch + 1 < NC);
    if (more) {
      int k0 = (ch + 1) << 4;
      a0 = *(const float4*)(Ap + k0);
      a1 = *(const float4*)(Ap + k0 + 4);
      b0 = *(const float4*)(Wp + k0);
      b1 = *(const float4*)(Wp + k0 + 4);
    }
#pragma unroll
    for (int kk = 0; kk < 16; kk++) {
      float4 av0 = *(const float4*)&xs[cur][kk][ty << 2];
      float4 av1 = *(const float4*)&xs[cur][kk][64 + (ty << 2)];
      float4 bv0 = *(const float4*)&ws[cur][kk][tx << 2];
      float4 bv1 = *(const float4*)&ws[cur][kk][64 + (tx << 2)];
      unsigned long long b2[4];
      b2[0] = pk2(bv0.x, bv0.y); b2[1] = pk2(bv0.z, bv0.w);
      b2[2] = pk2(bv1.x, bv1.y); b2[3] = pk2(bv1.z, bv1.w);
      float ar[8] = {av0.x, av0.y, av0.z, av0.w, av1.x, av1.y, av1.z, av1.w};
#pragma unroll
      for (int i = 0; i < 8; i++) {
        unsigned long long a2 = pk2(ar[i], ar[i]);
#pragma unroll
        for (int j = 0; j < 4; j++) fma2(acc[i][j], a2, b2[j]);
      }
    }
    if (more) {
      xs[nxt][lk8 + 0][lrow] = a0.x; xs[nxt][lk8 + 1][lrow] = a0.y;
      xs[nxt][lk8 + 2][lrow] = a0.z; xs[nxt][lk8 + 3][lrow] = a0.w;
      xs[nxt][lk8 + 4][lrow] = a1.x; xs[nxt][lk8 + 5][lrow] = a1.y;
      xs[nxt][lk8 + 6][lrow] = a1.z; xs[nxt][lk8 + 7][lrow] = a1.w;
      ws[nxt][lk8 + 0][lrow] = b0.x; ws[nxt][lk8 + 1][lrow] = b0.y;
      ws[nxt][lk8 + 2][lrow] = b0.z; ws[nxt][lk8 + 3][lrow] = b0.w;
      ws[nxt][lk8 + 4][lrow] = b1.x; ws[nxt][lk8 + 5][lrow] = b1.y;
      ws[nxt][lk8 + 6][lrow] = b1.z; ws[nxt][lk8 + 7][lrow] = b1.w;
      __syncthreads();
    }
  }
#pragma unroll
  for (int i = 0; i < 8; i++) {
    int r = row0 + ((i < 4) ? ((ty << 2) + i) : (64 + (ty << 2) + i - 4));
    int c0 = col0 + (tx << 2);
    int c1 = col0 + 64 + (tx << 2);
    float o[8];
#pragma unroll
    for (int j = 0; j < 4; j++) upk2(o[2 * j], o[2 * j + 1], acc[i][j]);
    *(float4*)(C + (size_t)r * N + c0) =
        make_float4(o[0] + bias[c0], o[1] + bias[c0 + 1],
                    o[2] + bias[c0 + 2], o[3] + bias[c0 + 3]);
    *(float4*)(C + (size_t)r * N + c1) =
        make_float4(o[4] + bias[c1], o[5] + bias[c1 + 1],
                    o[6] + bias[c1 + 2], o[7] + bias[c1 + 3]);
  }
}

// ------------- split fp32 -> fp16 hi/lo with exact pow2 pre-scale --------
__global__ void split_kernel(const float* __restrict__ in,
                             __half* __restrict__ hi, __half* __restrict__ lo,
                             float scale, int n4) {
  int i = blockIdx.x * blockDim.x + threadIdx.x;
  if (i < n4) {
    float4 v = ((const float4*)in)[i];
    v.x *= scale; v.y *= scale; v.z *= scale; v.w *= scale;
    __half hx = __float2half_rn(v.x), hy = __float2half_rn(v.y);
    __half hz = __float2half_rn(v.z), hw = __float2half_rn(v.w);
    __half lx = __float2half_rn(v.x - __half2float(hx));
    __half ly = __float2half_rn(v.y - __half2float(hy));
    __half lz = __float2half_rn(v.z - __half2float(hz));
    __half lw = __float2half_rn(v.w - __half2float(hw));
    __half2 h0 = __halves2half2(hx, hy), h1 = __halves2half2(hz, hw);
    __half2 l0 = __halves2half2(lx, ly), l1 = __halves2half2(lz, lw);
    ((uint2*)hi)[i] = make_uint2(*(uint32_t*)&h0, *(uint32_t*)&h1);
    ((uint2*)lo)[i] = make_uint2(*(uint32_t*)&l0, *(uint32_t*)&l1);
  }
}

// ------------- fp16 mma helper -------------------------------------------
__device__ __forceinline__ void mmaf16(float* c, const uint32_t* a,
                                       const uint32_t* b) {
  asm volatile(
      "mma.sync.aligned.m16n8k16.row.col.f32.f16.f16.f32 "
      "{%0,%1,%2,%3}, {%4,%5,%6,%7}, {%8,%9}, {%0,%1,%2,%3};"
      : "+f"(c[0]), "+f"(c[1]), "+f"(c[2]), "+f"(c[3])
      : "r"(a[0]), "r"(a[1]), "r"(a[2]), "r"(a[3]), "r"(b[0]), "r"(b[1]));
}

// ------------- 3-product fp16-split GEMM (decoder): C = inv*(A@W^T)+b ----
__global__ __launch_bounds__(256) void gemm3h(
    const __half* __restrict__ Ah, const __half* __restrict__ Al,
    const __half* __restrict__ Wh, const __half* __restrict__ Wl,
    const float* __restrict__ bias, float* __restrict__ C, float inv, int M,
    int N, int Kd) {
  __shared__ __align__(16) __half Ahs[128][40];
  __shared__ __align__(16) __half Als[128][40];
  __shared__ __align__(16) __half Whs[128][40];
  __shared__ __align__(16) __half Wls[128][40];
  int tid = threadIdx.x;
  int wid = tid >> 5, lane = tid & 31;
  int gid = lane >> 2, tig = lane & 3;
  int wm = wid & 1, wn = wid >> 1;
  int row0 = blockIdx.y << 7, col0 = blockIdx.x << 7;

  float acc[4][4][4];
#pragma unroll
  for (int mf = 0; mf < 4; mf++)
#pragma unroll
    for (int nf = 0; nf < 4; nf++)
#pragma unroll
      for (int q = 0; q < 4; q++) acc[mf][nf][q] = 0.f;

  for (int k0 = 0; k0 < Kd; k0 += 32) {
    __syncthreads();
#pragma unroll
    for (int l = 0; l < 2; l++) {
      int idx = tid + l * 256;
      int r = idx >> 2, c8 = (idx & 3) * 8;
      size_t ga = (size_t)(row0 + r) * Kd + k0 + c8;
      size_t gw = (size_t)(col0 + r) * Kd + k0 + c8;
      *(uint4*)&Ahs[r][c8] = *(const uint4*)(Ah + ga);
      *(uint4*)&Als[r][c8] = *(const uint4*)(Al + ga);
      *(uint4*)&Whs[r][c8] = *(const uint4*)(Wh + gw);
      *(uint4*)&Wls[r][c8] = *(const uint4*)(Wl + gw);
    }
    __syncthreads();

#pragma unroll
    for (int kk = 0; kk < 2; kk++) {
      int k16 = kk * 16;
      uint32_t ah[4][4], al[4][4];
#pragma unroll
      for (int mf = 0; mf < 4; mf++) {
        int R = wm * 64 + mf * 16;
        ah[mf][0] = *(const uint32_t*)&Ahs[R + gid][k16 + 2 * tig];
        ah[mf][1] = *(const uint32_t*)&Ahs[R + gid + 8][k16 + 2 * tig];
        ah[mf][2] = *(const uint32_t*)&Ahs[R + gid][k16 + 8 + 2 * tig];
        ah[mf][3] = *(const uint32_t*)&Ahs[R + gid + 8][k16 + 8 + 2 * tig];
        al[mf][0] = *(const uint32_t*)&Als[R + gid][k16 + 2 * tig];
        al[mf][1] = *(const uint32_t*)&Als[R + gid + 8][k16 + 2 * tig];
        al[mf][2] = *(const uint32_t*)&Als[R + gid][k16 + 8 + 2 * tig];
        al[mf][3] = *(const uint32_t*)&Als[R + gid + 8][k16 + 8 + 2 * tig];
      }
#pragma unroll
      for (int nf = 0; nf < 4; nf++) {
        int Cc = wn * 32 + nf * 8;
        uint32_t bh[2], bl[2];
        bh[0] = *(const uint32_t*)&Whs[Cc + gid][k16 + 2 * tig];
        bh[1] = *(const uint32_t*)&Whs[Cc + gid][k16 + 8 + 2 * tig];
        bl[0] = *(const uint32_t*)&Wls[Cc + gid][k16 + 2 * tig];
        bl[1] = *(const uint32_t*)&Wls[Cc + gid][k16 + 8 + 2 * tig];
#pragma unroll
        for (int mf = 0; mf < 4; mf++) {
          mmaf16(acc[mf][nf], ah[mf], bh);
          mmaf16(acc[mf][nf], ah[mf], bl);
          mmaf16(acc[mf][nf], al[mf], bh);
        }
      }
    }
  }

#pragma unroll
  for (int mf = 0; mf < 4; mf++) {
    int r0 = row0 + wm * 64 + mf * 16 + gid;
#pragma unroll
    for (int nf = 0; nf < 4; nf++) {
      int c = col0 + wn * 32 + nf * 8 + 2 * tig;
      float b0 = bias[c], b1 = bias[c + 1];
      float2 lo = make_float2(acc[mf][nf][0] * inv + b0,
                              acc[mf][nf][1] * inv + b1);
      float2 hi = make_float2(acc[mf][nf][2] * inv + b0,
                              acc[mf][nf][3] * inv + b1);
      *(float2*)(C + (size_t)r0 * N + c) = lo;
      *(float2*)(C + (size_t)(r0 + 8) * N + c) = hi;
    }
  }
}

// ------------- row sum-of-squares (order is load-bearing) ----------------
__global__ void rowsq_kernel(const float* __restrict__ in,
                             float* __restrict__ out, int nrows) {
  int w = (blockIdx.x * blockDim.x + threadIdx.x) >> 5;
  int lane = threadIdx.x & 31;
  if (w >= nrows) return;
  const float* p = in + (size_t)w * DD;
  float s = 0.f;
#pragma unroll
  for (int i = 0; i < 8; i++) { float v = p[lane + 32 * i]; s += v * v; }
#pragma unroll
  for (int o = 16; o; o >>= 1) s += __shfl_xor_sync(0xffffffffu, s, o);
  if (lane == 0) out[w] = s;
}

__global__ void zero_kernel(float* __restrict__ p, int n) {
  int i = blockIdx.x * blockDim.x + threadIdx.x;
  if (i < n) p[i] = 0.f;
}

__global__ void tobf16_kernel(const float* __restrict__ in,
                              __nv_bfloat16* __restrict__ out, int n4) {
  int i = blockIdx.x * blockDim.x + threadIdx.x;
  if (i < n4) {
    float4 v = ((const float4*)in)[i];
    __nv_bfloat162 a = __floats2bfloat162_rn(v.x, v.y);
    __nv_bfloat162 b = __floats2bfloat162_rn(v.z, v.w);
    ((uint2*)out)[i] = make_uint2(*(uint32_t*)&a, *(uint32_t*)&b);
  }
}

__device__ __forceinline__ unsigned long long packdk(float d, int k) {
  unsigned u = __float_as_uint(d);
  u = (u & 0x80000000u) ? ~u : (u | 0x80000000u);
  return ((unsigned long long)u << 32) | (unsigned)k;
}

// ------------- bf16 HMMA mma.sync helper ---------------------------------
__device__ __forceinline__ void mma16816(float* c, const uint32_t* a,
                                         const uint32_t* b) {
  asm volatile(
      "mma.sync.aligned.m16n8k16.row.col.f32.bf16.bf16.f32 "
      "{%0,%1,%2,%3}, {%4,%5,%6,%7}, {%8,%9}, {%0,%1,%2,%3};"
      : "+f"(c[0]), "+f"(c[1]), "+f"(c[2]), "+f"(c[3])
      : "r"(a[0]), "r"(a[1]), "r"(a[2]), "r"(a[3]), "r"(b[0]), "r"(b[1]));
}

// ------------- phase 1: approx cross GEMM on HMMA ------------------------
__global__ __launch_bounds__(256) void cross_mma_kernel(
    const __nv_bfloat16* __restrict__ zb, const __nv_bfloat16* __restrict__ cbb,
    __nv_bfloat16* __restrict__ capx) {
  __shared__ __align__(16) __nv_bfloat16 As[128][72];
  __shared__ __align__(16) __nv_bfloat16 Bs[128][72];
  int tid = threadIdx.x;
  int wid = tid >> 5, lane = tid & 31;
  int gid = lane >> 2, tig = lane & 3;
  int wm = wid & 1, wn = wid >> 1;
  int s = blockIdx.z, k0 = blockIdx.x << 7, b0 = blockIdx.y << 7;

  float acc[4][4][4];
#pragma unroll
  for (int mf = 0; mf < 4; mf++)
#pragma unroll
    for (int nf = 0; nf < 4; nf++)
#pragma unroll
      for (int q = 0; q < 4; q++) acc[mf][nf][q] = 0.f;

  for (int kc = 0; kc < 4; kc++) {
    int koff = kc * 64;
    __syncthreads();
#pragma unroll
    for (int l = 0; l < 4; l++) {
      int idx = tid + l * 256;
      int r = idx >> 3, c8 = idx & 7;
      uint4 va = *(const uint4*)(zb + (size_t)(b0 + r) * SD + s * DD + koff + c8 * 8);
      *(uint4*)&As[r][c8 * 8] = va;
      uint4 vb = *(const uint4*)(cbb + ((size_t)s * KK + k0 + r) * DD + koff + c8 * 8);
      *(uint4*)&Bs[r][c8 * 8] = vb;
    }
    __syncthreads();

#pragma unroll
    for (int kk = 0; kk < 4; kk++) {
      int k16 = kk * 16;
      uint32_t a[4][4];
#pragma unroll
      for (int mf = 0; mf < 4; mf++) {
        int R = wm * 64 + mf * 16;
        a[mf][0] = *(const uint32_t*)&As[R + gid][k16 + 2 * tig];
        a[mf][1] = *(const uint32_t*)&As[R + gid + 8][k16 + 2 * tig];
        a[mf][2] = *(const uint32_t*)&As[R + gid][k16 + 8 + 2 * tig];
        a[mf][3] = *(const uint32_t*)&As[R + gid + 8][k16 + 8 + 2 * tig];
      }
#pragma unroll
      for (int nf = 0; nf < 4; nf++) {
        int C = wn * 32 + nf * 8;
        uint32_t b[2];
        b[0] = *(const uint32_t*)&Bs[C + gid][k16 + 2 * tig];
        b[1] = *(const uint32_t*)&Bs[C + gid][k16 + 8 + 2 * tig];
#pragma unroll
        for (int mf = 0; mf < 4; mf++) mma16816(acc[mf][nf], a[mf], b);
      }
    }
  }

#pragma unroll
  for (int mf = 0; mf < 4; mf++) {
    int row0 = wm * 64 + mf * 16 + gid;
#pragma unroll
    for (int nf = 0; nf < 4; nf++) {
      int col = k0 + wn * 32 + nf * 8 + 2 * tig;
      __nv_bfloat162 lo = __floats2bfloat162_rn(acc[mf][nf][0], acc[mf][nf][1]);
      __nv_bfloat162 hi = __floats2bfloat162_rn(acc[mf][nf][2], acc[mf][nf][3]);
      size_t g0 = ((size_t)s * BB + b0 + row0) * KK + col;
      size_t g1 = ((size_t)s * BB + b0 + row0 + 8) * KK + col;
      *(uint32_t*)(capx + g0) = *(uint32_t*)&lo;
      *(uint32_t*)(capx + g1) = *(uint32_t*)&hi;
    }
  }
}

// ------------- phase 2: scan + exact recheck of candidates ---------------
__global__ __launch_bounds__(256) void scan_kernel(
    const float* __restrict__ z, const float* __restrict__ cb,
    const __nv_bfloat16* __restrict__ capx, const float* __restrict__ zsq,
    const float* __restrict__ esq, int* __restrict__ codes,
    int* __restrict__ flags) {
  __shared__ __align__(16) __nv_bfloat16 crow[KK];
  __shared__ float zrow[DD];
  __shared__ float redf[8];
  __shared__ float bmax;
  __shared__ int cnt;
  __shared__ int cand[CAP];
  __shared__ unsigned long long packs[CAP];
  int srow = blockIdx.x;
  int s = srow >> 12, b = srow & 4095;
  int tid = threadIdx.x;
  const uint4* src = (const uint4*)(capx + (size_t)srow * KK);
  uint4* dc = (uint4*)crow;
#pragma unroll
  for (int l = 0; l < 4; l++) dc[tid + l * 256] = src[tid + l * 256];
  zrow[tid] = z[(size_t)b * SD + s * DD + tid];
  if (tid == 0) cnt = 0;
  __syncthreads();

  float mx = -1e30f;
#pragma unroll
  for (int l = 0; l < 32; l++)
    mx = fmaxf(mx, __bfloat162float(crow[tid + l * 256]));
#pragma unroll
  for (int o = 16; o; o >>= 1) mx = fmaxf(mx, __shfl_xor_sync(~0u, mx, o));
  if ((tid & 31) == 0) redf[tid >> 5] = mx;
  __syncthreads();
  if (tid == 0) {
    float m = redf[0];
#pragma unroll
    for (int i = 1; i < 8; i++) m = fmaxf(m, redf[i]);
    bmax = m;
  }
  __syncthreads();
  float th = bmax - MARGIN;
#pragma unroll
  for (int l = 0; l < 32; l++) {
    int k = tid + l * 256;
    if (__bfloat162float(crow[k]) >= th) {
      int p = atomicAdd(&cnt, 1);
      if (p < CAP) cand[p] = k;
    }
  }
  __syncthreads();
  int n = cnt;
  if (tid == 0) flags[srow] = (n > CAP) ? 1 : 0;
  if (n > CAP) return;

  if (tid < n) {
    int k = cand[tid];
    const float* e = cb + ((size_t)s * KK + k) * DD;
    float acc = 0.f;
#pragma unroll 8
    for (int d = 0; d < DD; d += 4) {
      float4 ev = *(const float4*)(e + d);
      acc = fmaf(zrow[d + 0], ev.x, acc);
      acc = fmaf(zrow[d + 1], ev.y, acc);
      acc = fmaf(zrow[d + 2], ev.z, acc);
      acc = fmaf(zrow[d + 3], ev.w, acc);
    }
    float t = zsq[b * SS + s] + esq[s * KK + k];
    float dv = t - 2.0f * acc;
    packs[tid] = packdk(dv, k);
  }
  __syncthreads();
  if (tid == 0) {
    unsigned long long m = packs[0];
    for (int i = 1; i < n; i++) { unsigned long long v = packs[i]; if (v < m) m = v; }
    codes[b * SS + s] = (int)(m & 0xffffffffULL);
  }
}

// ------------- fallback: full exact scan for overflowed rows -------------
__global__ __launch_bounds__(256) void fallback_kernel(
    const float* __restrict__ z, const float* __restrict__ cb,
    const float* __restrict__ zsq, const float* __restrict__ esq,
    int* __restrict__ codes, const int* __restrict__ flags) {
  if (!flags[blockIdx.x]) return;
  __shared__ float zrow[DD];
  __shared__ unsigned long long red[256];
  int srow = blockIdx.x;
  int s = srow >> 12, b = srow & 4095;
  int tid = threadIdx.x;
  zrow[tid] = z[(size_t)b * SD + s * DD + tid];
  __syncthreads();
  float zsqv = zsq[b * SS + s];
  unsigned long long best = ~0ull;
  for (int j = 0; j < 32; j++) {
    int k = tid + j * 256;
    const float* e = cb + ((size_t)s * KK + k) * DD;
    float acc = 0.f;
#pragma unroll 8
    for (int d = 0; d < DD; d += 4) {
      float4 ev = *(const float4*)(e + d);
      acc = fmaf(zrow[d + 0], ev.x, acc);
      acc = fmaf(zrow[d + 1], ev.y, acc);
      acc = fmaf(zrow[d + 2], ev.z, acc);
      acc = fmaf(zrow[d + 3], ev.w, acc);
    }
    float dv = (zsqv + esq[s * KK + k]) - 2.0f * acc;
    unsigned long long p = packdk(dv, k);
    if (p < best) best = p;
  }
  red[tid] = best;
  __syncthreads();
  for (int o = 128; o; o >>= 1) {
    if (tid < o) { unsigned long long v = red[tid + o]; if (v < red[tid]) red[tid] = v; }
    __syncthreads();
  }
  if (tid == 0) codes[b * SS + s] = (int)(red[0] & 0xffffffffULL);
}

// ------------- tail kernels ----------------------------------------------
__global__ void gather_kernel(const float* __restrict__ cb,
                              const int* __restrict__ codes,
                              float* __restrict__ quant) {
  int i = blockIdx.x * blockDim.x + threadIdx.x;
  int b = i >> 9, rem = i & 511;
  int s = rem >> 6, d4 = rem & 63;
  int code = codes[b * SS + s];
  float4 v = *(const float4*)(cb + ((size_t)(s * KK + code)) * DD + (d4 << 2));
  *(float4*)(quant + (size_t)b * SD + s * DD + (d4 << 2)) = v;
}

__global__ void count_kernel(const int* __restrict__ codes,
                             float* __restrict__ counts) {
  int i = blockIdx.x * blockDim.x + threadIdx.x;
  if (i < BB * SS) {
    int s = i & 7;
    atomicAdd(&counts[s * KK + codes[i]], 1.0f);
  }
}

__global__ void perp_kernel(const float* __restrict__ counts,
                            float* __restrict__ outp) {
  __shared__ float sh[256];
  __shared__ float perps;
  int tid = threadIdx.x;
  if (tid == 0) perps = 0.f;
  for (int s = 0; s < SS; s++) {
    float local = 0.f;
    for (int k = tid; k < KK; k += 256) {
      float p = counts[s * KK + k] * (1.0f / BB);
      local += p * logf(p + 1e-10f);
    }
    sh[tid] = local;
    __syncthreads();
    for (int o = 128; o; o >>= 1) {
      if (tid < o) sh[tid] += sh[tid + o];
      __syncthreads();
    }
    if (tid == 0) perps += expf(-sh[0]);
    __syncthreads();
  }
  if (tid == 0) *outp = perps * (1.0f / SS);
}

__global__ void copy4_kernel(float* __restrict__ dst,
                             const float* __restrict__ src, int n4) {
  int i = blockIdx.x * blockDim.x + threadIdx.x;
  if (i < n4) ((float4*)dst)[i] = ((const float4*)src)[i];
}

__global__ void codesf_kernel(float* __restrict__ dst,
                              const int* __restrict__ codes, int n) {
  int i = blockIdx.x * blockDim.x + threadIdx.x;
  if (i < n) dst[i] = (float)codes[i];
}

// --------------------------------------------------------------------------
extern "C" void kernel_launch(void* const* d_in, const int* in_sizes, int n_in,
                              void* d_out, int out_size) {
  const float* x     = (const float*)d_in[0];
  const float* enc_w = (const float*)d_in[1];
  const float* enc_b = (const float*)d_in[2];
  const float* cb    = (const float*)d_in[3];
  const float* dec_w = (const float*)d_in[4];
  const float* dec_b = (const float*)d_in[5];

  float *z, *quant, *recon, *zsq, *esq, *counts;
  int *codes, *flags;
  __nv_bfloat16 *zb, *cbb, *capx;
  __half *dwh, *dwl, *qh, *ql;
  cudaGetSymbolAddress((void**)&z, g_z);
  cudaGetSymbolAddress((void**)&quant, g_quant);
  cudaGetSymbolAddress((void**)&recon, g_recon);
  cudaGetSymbolAddress((void**)&zsq, g_zsq);
  cudaGetSymbolAddress((void**)&esq, g_esq);
  cudaGetSymbolAddress((void**)&counts, g_counts);
  cudaGetSymbolAddress((void**)&codes, g_codes);
  cudaGetSymbolAddress((void**)&flags, g_flags);
  cudaGetSymbolAddress((void**)&zb, g_zb);
  cudaGetSymbolAddress((void**)&cbb, g_cbb);
  cudaGetSymbolAddress((void**)&capx, g_capx);
  cudaGetSymbolAddress((void**)&dwh, g_dwh);
  cudaGetSymbolAddress((void**)&dwl, g_dwl);
  cudaGetSymbolAddress((void**)&qh, g_qh);
  cudaGetSymbolAddress((void**)&ql, g_ql);

  const int offQ = BB * IND;
  const int offC = offQ + BB * SD;
  const int offP = offC + BB * SS;
  float* out = (float*)d_out;
  float* reconDst = (out_size >= offQ) ? out : recon;

  // 1. encoder (fp32x2 packed FFMA, FROZEN chain, double-buffered smem)
  gemm128x2<<<dim3(SD / 128, BB / 128), 256>>>(x, enc_w, enc_b, z,
                                               BB, SD, IND);
  // 2. norms (unchanged reduction order)
  rowsq_kernel<<<BB * SS / 8, 256>>>(z, zsq, BB * SS);
  rowsq_kernel<<<SS * KK / 8, 256>>>(cb, esq, SS * KK);
  // 3. bf16 conversions for filter
  tobf16_kernel<<<BB * SD / 4 / 256, 256>>>(z, zb, BB * SD / 4);
  tobf16_kernel<<<SS * KK * DD / 4 / 256, 256>>>(cb, cbb, SS * KK * DD / 4);
  // 4. approx cross on HMMA tensor cores
  cross_mma_kernel<<<dim3(KK / 128, BB / 128, SS), 256>>>(zb, cbb, capx);
  // 5. scan + exact candidate recheck
  scan_kernel<<<BB * SS, 256>>>(z, cb, capx, zsq, esq, codes, flags);
  fallback_kernel<<<BB * SS, 256>>>(z, cb, zsq, esq, codes, flags);
  // 6. gather + counts
  gather_kernel<<<BB * SD / 4 / 256, 256>>>(cb, codes, quant);
  zero_kernel<<<SS * KK / 256, 256>>>(counts, SS * KK);
  count_kernel<<<BB * SS / 256, 256>>>(codes, counts);
  // 7. decoder (scaled fp16x3 tensor cores): x_recon = quant@dec_w^T + b
  split_kernel<<<IND * SD / 4 / 256, 256>>>(dec_w, dwh, dwl, 32.f,
                                            IND * SD / 4);
  split_kernel<<<BB * SD / 4 / 256, 256>>>(quant, qh, ql, 8192.f,
                                           BB * SD / 4);
  gemm3h<<<dim3(IND / 128, BB / 128), 256>>>(qh, ql, dwh, dwl, dec_b, reconDst,
                                             1.f / (8192.f * 32.f),
                                             BB, IND, SD);
  // 8. tuple tail
  if (out_size >= offC)
    copy4_kernel<<<BB * SD / 4 / 256, 256>>>(out + offQ, quant, BB * SD / 4);
  if (out_size >= offP)
    codesf_kernel<<<BB * SS / 256, 256>>>(out + offC, codes, BB * SS);
  if (out_size >= offP + 1)
    perp_kernel<<<1, 256>>>(counts, out + offP);
}